// round 13
// baseline (speedup 1.0000x reference)
#include <cuda_runtime.h>
#include <cuda_bf16.h>
#include <math.h>
#include <float.h>
#include <stdint.h>

constexpr int Bn   = 16;
constexpr int Sn   = 512;
constexpr int Dn   = 512;
constexpr int Hn   = 8;
constexpr int DKn  = 64;
constexpr int DFFn = 2048;
constexpr int BSn  = Bn * Sn;          // 8192 rows
constexpr int Ln   = 6;

typedef __nv_bfloat16 bf16;

// ---------------- fp32 scratch ----------------
__device__ float g_x  [BSn*Dn];
__device__ float g_y  [BSn*Dn];
__device__ float g_tmp[BSn*Dn];
__device__ float g_sc [(size_t)Bn*Hn*Sn*Sn];   // 128 MB scores

// ---------------- bf16 split scratch ----------------
__device__ __align__(128) bf16 g_xh[BSn*Dn],  g_xl[BSn*Dn];
__device__ __align__(128) bf16 g_yh[BSn*Dn],  g_yl[BSn*Dn];
__device__ __align__(128) bf16 g_qkh[BSn*Dn], g_qkl[BSn*Dn];
__device__ __align__(128) bf16 g_vph[BSn*Dn], g_vpl[BSn*Dn];
__device__ __align__(128) bf16 g_ah[BSn*Dn],  g_al[BSn*Dn];
__device__ __align__(128) bf16 g_fh[BSn*DFFn],g_fl[BSn*DFFn];
__device__ __align__(128) bf16 g_ph[(size_t)Bn*Hn*Sn*Sn];   // probs hi
__device__ __align__(128) bf16 g_pl[(size_t)Bn*Hn*Sn*Sn];   // probs lo
// transposed split weights: [N,K] row-major
__device__ __align__(128) bf16 g_wkh[Ln*Dn*Dn],   g_wkl[Ln*Dn*Dn];
__device__ __align__(128) bf16 g_wvh[Ln*Dn*Dn],   g_wvl[Ln*Dn*Dn];
__device__ __align__(128) bf16 g_woh[Ln*Dn*Dn],   g_wol[Ln*Dn*Dn];
__device__ __align__(128) bf16 g_w1h[Ln*Dn*DFFn], g_w1l[Ln*Dn*DFFn];
__device__ __align__(128) bf16 g_w2h[Ln*DFFn*Dn], g_w2l[Ln*DFFn*Dn];

// ---------------- low-level helpers ----------------
__device__ __forceinline__ uint32_t smem_u32(const void* p){
    return (uint32_t)__cvta_generic_to_shared(p);
}
__device__ __forceinline__ void cp16(uint32_t dst, const void* src){
    asm volatile("cp.async.cg.shared.global [%0], [%1], 16;"
                 :: "r"(dst), "l"(src));
}
__device__ __forceinline__ void cp_commit(){
    asm volatile("cp.async.commit_group;" ::: "memory");
}
template<int N>
__device__ __forceinline__ void cp_waitg(){
    asm volatile("cp.async.wait_group %0;" :: "n"(N) : "memory");
}
__device__ __forceinline__ void ldm_x4(uint32_t* r, uint32_t addr){
    asm volatile("ldmatrix.sync.aligned.m8n8.x4.shared.b16 {%0,%1,%2,%3}, [%4];"
                 : "=r"(r[0]),"=r"(r[1]),"=r"(r[2]),"=r"(r[3]) : "r"(addr));
}
__device__ __forceinline__ void ldm_x4_t(uint32_t* r, uint32_t addr){
    asm volatile("ldmatrix.sync.aligned.m8n8.x4.trans.shared.b16 {%0,%1,%2,%3}, [%4];"
                 : "=r"(r[0]),"=r"(r[1]),"=r"(r[2]),"=r"(r[3]) : "r"(addr));
}
__device__ __forceinline__ void mma_bf16(float* c, const uint32_t* a,
                                         const uint32_t* b){
    asm volatile("mma.sync.aligned.m16n8k16.row.col.f32.bf16.bf16.f32 "
        "{%0,%1,%2,%3}, {%4,%5,%6,%7}, {%8,%9}, {%0,%1,%2,%3};"
        : "+f"(c[0]),"+f"(c[1]),"+f"(c[2]),"+f"(c[3])
        : "r"(a[0]),"r"(a[1]),"r"(a[2]),"r"(a[3]), "r"(b[0]),"r"(b[1]));
}
__device__ __forceinline__ void split2(float v0, float v1,
                                       __nv_bfloat162& hp, __nv_bfloat162& lp){
    bf16 h0 = __float2bfloat16(v0), h1 = __float2bfloat16(v1);
    hp.x = h0; hp.y = h1;
    lp.x = __float2bfloat16(v0 - __bfloat162float(h0));
    lp.y = __float2bfloat16(v1 - __bfloat162float(h1));
}
__device__ __forceinline__ float warp_sum(float v){
    #pragma unroll
    for (int o = 16; o > 0; o >>= 1) v += __shfl_xor_sync(0xffffffffu, v, o);
    return v;
}
__device__ __forceinline__ float warp_max(float v){
    #pragma unroll
    for (int o = 16; o > 0; o >>= 1) v = fmaxf(v, __shfl_xor_sync(0xffffffffu, v, o));
    return v;
}
__device__ __forceinline__ float block_sum(float v, float* red){
    int lane = threadIdx.x & 31, w = threadIdx.x >> 5, nw = blockDim.x >> 5;
    v = warp_sum(v);
    if (lane == 0) red[w] = v;
    __syncthreads();
    if (w == 0){
        float r = (lane < nw) ? red[lane] : 0.f;
        r = warp_sum(r);
        if (lane == 0) red[0] = r;
    }
    __syncthreads();
    float out = red[0];
    __syncthreads();
    return out;
}

constexpr int HG_STAGE = 32768;              // A(16K)+B(16K) per stage
constexpr int HG_SMEM  = 3*HG_STAGE;         // 96 KB dynamic (3-stage)
constexpr int AV_STAGE = 24576;              // P(16K)+V(8K)
constexpr int AV_SMEM  = 2*AV_STAGE;         // 48 KB
constexpr int QK_SMEM  = 65536;              // Ah,Al,Bh,Bl 16K each

// ---------------- HMMA split-bf16 GEMM body (3-stage pipeline) ---------------
// C[M,N] = A[M,K] @ B^T (B stored [N,K]); 3 passes Ah*Bh+Ah*Bl+Al*Bh.
template<bool RELU, bool SPLIT, bool WF32>
__device__ __forceinline__ void hgemm_body(
    const bf16* __restrict__ Ah, const bf16* __restrict__ Al,
    const bf16* __restrict__ Bh, const bf16* __restrict__ Bl,
    const float* __restrict__ bias, float* __restrict__ C,
    bf16* __restrict__ Ch, bf16* __restrict__ Cl, int N, int K)
{
    extern __shared__ char smem[];
    uint32_t sb = smem_u32(smem);
    int tid = threadIdx.x, lane = tid & 31, wid = tid >> 5;
    int wm = (wid >> 2) * 64, wn = (wid & 3) * 32;
    int n0 = blockIdx.x * 128, m0 = blockIdx.y * 128;

    const int CH = K >> 6;
    const int T  = 3 * CH;

    float acc[4][4][4];
    #pragma unroll
    for (int i = 0; i < 4; i++)
        #pragma unroll
        for (int j = 0; j < 4; j++)
            #pragma unroll
            for (int q = 0; q < 4; q++) acc[i][j][q] = 0.f;

    auto preload = [&](int t){
        int p = t / CH, c = t % CH, k0 = c << 6;
        const bf16* Asrc = (p < 2)  ? Ah : Al;
        const bf16* Bsrc = (p == 1) ? Bl : Bh;
        int s = t % 3;
        uint32_t buf = sb + s * HG_STAGE;
        #pragma unroll
        for (int g = tid; g < 1024; g += 256){
            int r = g >> 3, ch = g & 7;
            cp16(buf + (r << 7) + ((ch ^ (r & 7)) << 4),
                 Asrc + (size_t)(m0 + r) * K + k0 + ch * 8);
        }
        #pragma unroll
        for (int g = tid; g < 1024; g += 256){
            int r = g >> 3, ch = g & 7;
            cp16(buf + 16384 + (r << 7) + ((ch ^ (r & 7)) << 4),
                 Bsrc + (size_t)(n0 + r) * K + k0 + ch * 8);
        }
        cp_commit();
    };

    preload(0);
    preload(1);
    for (int t = 0; t < T; t++){
        if (t + 1 < T) cp_waitg<1>(); else cp_waitg<0>();
        __syncthreads();
        if (t + 2 < T) preload(t + 2);

        uint32_t abuf = sb + (t % 3) * HG_STAGE;
        uint32_t bbuf = abuf + 16384;
        #pragma unroll
        for (int kk = 0; kk < 4; kk++){
            uint32_t af[4][4];
            #pragma unroll
            for (int mt = 0; mt < 4; mt++){
                int m = wm + mt*16 + (lane & 7) + ((lane >> 3) & 1) * 8;
                int kc = kk*2 + (lane >> 4);
                ldm_x4(af[mt], abuf + (m << 7) + ((kc ^ (m & 7)) << 4));
            }
            uint32_t bfr[2][4];
            #pragma unroll
            for (int pr = 0; pr < 2; pr++){
                int n = wn + pr*16 + (lane & 7) + (lane >> 4) * 8;
                int kc = kk*2 + ((lane >> 3) & 1);
                ldm_x4(bfr[pr], bbuf + (n << 7) + ((kc ^ (n & 7)) << 4));
            }
            #pragma unroll
            for (int mt = 0; mt < 4; mt++)
                #pragma unroll
                for (int nt = 0; nt < 4; nt++)
                    mma_bf16(acc[mt][nt], af[mt], &bfr[nt >> 1][(nt & 1) * 2]);
        }
        __syncthreads();
    }

    int qrow = lane >> 2, qcol = (lane & 3) * 2;
    #pragma unroll
    for (int mt = 0; mt < 4; mt++){
        #pragma unroll
        for (int nt = 0; nt < 4; nt++){
            int m = m0 + wm + mt*16 + qrow;
            int n = n0 + wn + nt*8 + qcol;
            float b0 = bias[n], b1 = bias[n+1];
            #pragma unroll
            for (int half = 0; half < 2; half++){
                int mm = m + half*8;
                float v0 = acc[mt][nt][half*2]   + b0;
                float v1 = acc[mt][nt][half*2+1] + b1;
                if (RELU){ v0 = fmaxf(v0, 0.f); v1 = fmaxf(v1, 0.f); }
                if (WF32){
                    float2 fv; fv.x = v0; fv.y = v1;
                    *(float2*)(C + (size_t)mm*N + n) = fv;
                }
                if (SPLIT){
                    __nv_bfloat162 hp, lp;
                    split2(v0, v1, hp, lp);
                    *(__nv_bfloat162*)(Ch + (size_t)mm*N + n) = hp;
                    *(__nv_bfloat162*)(Cl + (size_t)mm*N + n) = lp;
                }
            }
        }
    }
}

template<bool RELU, bool SPLIT, bool WF32>
__global__ void __launch_bounds__(256) hgemm(
    const bf16* __restrict__ Ah, const bf16* __restrict__ Al,
    const bf16* __restrict__ Bh, const bf16* __restrict__ Bl,
    const float* __restrict__ bias, float* __restrict__ C,
    bf16* __restrict__ Ch, bf16* __restrict__ Cl, int N, int K)
{
    hgemm_body<RELU,SPLIT,WF32>(Ah,Al,Bh,Bl,bias,C,Ch,Cl,N,K);
}

// merged Q/K + V projections: POINTER select by z, single body call.
__global__ void __launch_bounds__(256) hgemm_proj(
    const bf16* __restrict__ A0h, const bf16* __restrict__ A0l,
    const bf16* __restrict__ B0h, const bf16* __restrict__ B0l,
    const float* __restrict__ bias0, bf16* __restrict__ C0h, bf16* __restrict__ C0l,
    const bf16* __restrict__ A1h, const bf16* __restrict__ A1l,
    const bf16* __restrict__ B1h, const bf16* __restrict__ B1l,
    const float* __restrict__ bias1, bf16* __restrict__ C1h, bf16* __restrict__ C1l,
    int N, int K)
{
    bool z = (blockIdx.z != 0);
    const bf16* Ah = z ? A1h : A0h;
    const bf16* Al = z ? A1l : A0l;
    const bf16* Bh = z ? B1h : B0h;
    const bf16* Bl = z ? B1l : B0l;
    const float* bias = z ? bias1 : bias0;
    bf16* Ch = z ? C1h : C0h;
    bf16* Cl = z ? C1l : C0l;
    hgemm_body<false,true,false>(Ah,Al,Bh,Bl,bias,nullptr,Ch,Cl,N,K);
}

// ---------------- QK^T via HMMA: 128x128 tiles, K=64, triangular skip -------
__global__ void __launch_bounds__(256) qk_hmma(
    const bf16* __restrict__ qkh, const bf16* __restrict__ qkl,
    float* __restrict__ sc)
{
    int jt = blockIdx.x, it = blockIdx.y;
    if (jt > it) return;
    int bh = blockIdx.z, b = bh >> 3, h = bh & 7;
    int i0 = it * 128, j0 = jt * 128;

    extern __shared__ char smem[];
    uint32_t sb = smem_u32(smem);
    int tid = threadIdx.x, lane = tid & 31, wid = tid >> 5;

    const bf16* bh_ = qkh + (size_t)b*Sn*Dn + h*DKn;
    const bf16* bl_ = qkl + (size_t)b*Sn*Dn + h*DKn;
    for (int g = tid; g < 1024; g += 256){
        int r = g >> 3, ch = g & 7;
        uint32_t sw = (r << 7) + ((ch ^ (r & 7)) << 4);
        cp16(sb +         sw, bh_ + (size_t)(i0+r)*Dn + ch*8);
        cp16(sb + 16384 + sw, bl_ + (size_t)(i0+r)*Dn + ch*8);
        cp16(sb + 32768 + sw, bh_ + (size_t)(j0+r)*Dn + ch*8);
        cp16(sb + 49152 + sw, bl_ + (size_t)(j0+r)*Dn + ch*8);
    }
    cp_commit(); cp_waitg<0>();
    __syncthreads();

    int wm = (wid >> 2) * 64, wn = (wid & 3) * 32;
    float acc[4][4][4];
    #pragma unroll
    for (int i = 0; i < 4; i++)
        #pragma unroll
        for (int j = 0; j < 4; j++)
            #pragma unroll
            for (int q = 0; q < 4; q++) acc[i][j][q] = 0.f;

    #pragma unroll
    for (int p = 0; p < 3; p++){
        uint32_t abuf = sb + ((p < 2) ? 0 : 16384);
        uint32_t bbuf = sb + 32768 + ((p == 1) ? 16384 : 0);
        #pragma unroll
        for (int kk = 0; kk < 4; kk++){
            uint32_t af[4][4];
            #pragma unroll
            for (int mt = 0; mt < 4; mt++){
                int m = wm + mt*16 + (lane & 7) + ((lane >> 3) & 1) * 8;
                int kc = kk*2 + (lane >> 4);
                ldm_x4(af[mt], abuf + (m << 7) + ((kc ^ (m & 7)) << 4));
            }
            uint32_t bfr[2][4];
            #pragma unroll
            for (int pr = 0; pr < 2; pr++){
                int n = wn + pr*16 + (lane & 7) + (lane >> 4) * 8;
                int kc = kk*2 + ((lane >> 3) & 1);
                ldm_x4(bfr[pr], bbuf + (n << 7) + ((kc ^ (n & 7)) << 4));
            }
            #pragma unroll
            for (int mt = 0; mt < 4; mt++)
                #pragma unroll
                for (int nt = 0; nt < 4; nt++)
                    mma_bf16(acc[mt][nt], af[mt], &bfr[nt >> 1][(nt & 1) * 2]);
        }
    }

    float* out = sc + (size_t)bh * Sn * Sn;
    int qrow = lane >> 2, qcol = (lane & 3) * 2;
    #pragma unroll
    for (int mt = 0; mt < 4; mt++)
        #pragma unroll
        for (int nt = 0; nt < 4; nt++)
            #pragma unroll
            for (int half = 0; half < 2; half++){
                int i = i0 + wm + mt*16 + qrow + half*8;
                int j = j0 + wn + nt*8 + qcol;
                float2 fv;
                fv.x = acc[mt][nt][half*2]   * 0.125f;
                fv.y = acc[mt][nt][half*2+1] * 0.125f;
                *(float2*)(out + (size_t)i*Sn + j) = fv;
            }
}

// ---------------- attn@V via HMMA (split probs x split V, trans-B) ----------
__global__ void __launch_bounds__(256) av_hmma(
    const bf16* __restrict__ ph, const bf16* __restrict__ pl,
    const bf16* __restrict__ vh, const bf16* __restrict__ vl,
    bf16* __restrict__ ah, bf16* __restrict__ al)
{
    int it = gridDim.x - 1 - blockIdx.x;     // big tiles scheduled first
    int bh = blockIdx.y, b = bh >> 3, h = bh & 7;
    int i0 = it * 128;

    extern __shared__ char smem[];
    uint32_t sb = smem_u32(smem);
    int tid = threadIdx.x, lane = tid & 31, wid = tid >> 5;

    const bf16* Ph = ph + (size_t)bh * Sn * Sn;
    const bf16* Pl = pl + (size_t)bh * Sn * Sn;
    const bf16* Vh = vh + (size_t)b*Sn*Dn + h*DKn;
    const bf16* Vl = vl + (size_t)b*Sn*Dn + h*DKn;

    const int nch = (it + 1) * 2;   // 64-wide j chunks
    const int T = 3 * nch;

    float acc[2][4][4];
    #pragma unroll
    for (int i = 0; i < 2; i++)
        #pragma unroll
        for (int j = 0; j < 4; j++)
            #pragma unroll
            for (int q = 0; q < 4; q++) acc[i][j][q] = 0.f;

    auto preload = [&](int t){
        int p = t / nch, c = t % nch, j0 = c << 6;
        const bf16* Ps = (p < 2)  ? Ph : Pl;
        const bf16* Vs = (p == 1) ? Vl : Vh;
        uint32_t buf = sb + (t & 1) * AV_STAGE;
        #pragma unroll
        for (int g = tid; g < 1024; g += 256){
            int r = g >> 3, ch = g & 7;
            cp16(buf + (r << 7) + ((ch ^ (r & 7)) << 4),
                 Ps + (size_t)(i0 + r) * Sn + j0 + ch * 8);
        }
        #pragma unroll
        for (int g = tid; g < 512; g += 256){
            int r = g >> 3, ch = g & 7;
            cp16(buf + 16384 + (r << 7) + ((ch ^ (r & 7)) << 4),
                 Vs + (size_t)(j0 + r) * Dn + ch * 8);
        }
        cp_commit();
    };

    preload(0);
    int wm = (wid >> 1) * 32, wn = (wid & 1) * 32;
    for (int t = 0; t < T; t++){
        cp_waitg<0>();
        __syncthreads();
        if (t + 1 < T) preload(t + 1);

        uint32_t pb = sb + (t & 1) * AV_STAGE;
        uint32_t vb = pb + 16384;
        #pragma unroll
        for (int kk = 0; kk < 4; kk++){
            uint32_t af[2][4];
            #pragma unroll
            for (int mt = 0; mt < 2; mt++){
                int m = wm + mt*16 + (lane & 7) + ((lane >> 3) & 1) * 8;
                int kc = kk*2 + (lane >> 4);
                ldm_x4(af[mt], pb + (m << 7) + ((kc ^ (m & 7)) << 4));
            }
            uint32_t bfr[2][4];
            #pragma unroll
            for (int ng = 0; ng < 2; ng++){
                int row  = kk*16 + (lane & 7) + ((lane >> 3) & 1) * 8;
                int ncol = wn + ng*16 + ((lane >> 4) & 1) * 8;
                ldm_x4_t(bfr[ng], vb + (row << 7) + (((ncol >> 3) ^ (row & 7)) << 4));
            }
            #pragma unroll
            for (int mt = 0; mt < 2; mt++)
                #pragma unroll
                for (int nt = 0; nt < 4; nt++)
                    mma_bf16(acc[mt][nt], af[mt], &bfr[nt >> 1][(nt & 1) * 2]);
        }
        __syncthreads();
    }

    int qrow = lane >> 2, qcol = (lane & 3) * 2;
    #pragma unroll
    for (int mt = 0; mt < 2; mt++)
        #pragma unroll
        for (int nt = 0; nt < 4; nt++)
            #pragma unroll
            for (int half = 0; half < 2; half++){
                int i = i0 + wm + mt*16 + qrow + half*8;
                int d = wn + nt*8 + qcol;
                size_t off = (size_t)(b*Sn + i) * Dn + h*DKn + d;
                __nv_bfloat162 hp, lp;
                split2(acc[mt][nt][half*2], acc[mt][nt][half*2+1], hp, lp);
                *(__nv_bfloat162*)(ah + off) = hp;
                *(__nv_bfloat162*)(al + off) = lp;
            }
}

// ---------------- fused attention row pass (warp per row) -------------------
__global__ __launch_bounds__(256)
void attn_row(const float* __restrict__ sc, bf16* __restrict__ ph,
              bf16* __restrict__ pl, const float* __restrict__ gamma,
              int maskflag)
{
    const unsigned FULL = 0xffffffffu;
    int warp = (blockIdx.x * blockDim.x + threadIdx.x) >> 5;
    int lane = threadIdx.x & 31;
    int i = warp & (Sn-1);
    int h = (warp >> 9) & (Hn-1);
    const float* row = sc + (size_t)warp * Sn;
    int jbase = lane * 16;
    int jlim = ((i >> 7) + 1) << 7;
    bool act = jbase < jlim;
    int lim = maskflag ? i : (i - 1);

    float s[16];
    if (act){
        #pragma unroll
        for (int q = 0; q < 4; q++)
            *(float4*)&s[q*4] = *(const float4*)(row + jbase + q*4);
    } else {
        #pragma unroll
        for (int t = 0; t < 16; t++) s[t] = 0.f;
    }

    float m = -FLT_MAX;
    #pragma unroll
    for (int t = 0; t < 16; t++) if (jbase + t <= lim) m = fmaxf(m, s[t]);
    m = warp_max(m);

    float e[16]; float sum = 0.f;
    #pragma unroll
    for (int t = 0; t < 16; t++){
        e[t] = (jbase + t <= lim) ? __expf(s[t] - m) : 0.f;
        sum += e[t];
    }
    sum = warp_sum(sum);
    float inv1 = (sum > 0.f) ? 1.f / sum : 0.f;

    float c[16]; float run = 0.f;
    #pragma unroll
    for (int t = 0; t < 16; t++){ run += e[t]; c[t] = run; }
    float incl = run;
    #pragma unroll
    for (int o = 1; o < 32; o <<= 1){
        float tsh = __shfl_up_sync(FULL, incl, o);
        if (lane >= o) incl += tsh;
    }
    float excl = incl - run;

    float gm = gamma[h];
    float sp = (gm > 20.f) ? gm : log1pf(__expf(gm));
    float fi = (float)i;

    float s2[16];
    #pragma unroll
    for (int t = 0; t < 16; t++){
        float cumincl = excl + c[t];
        float rem = fmaxf(sum - cumincl, 0.f) * inv1;
        float pos = fabsf(fi - (float)(jbase + t));
        float dist = sqrtf(rem * pos);
        float eff = fminf(fmaxf(__expf(-sp * dist), 1e-5f), 1e5f);
        s2[t] = s[t] * eff;
    }

    float m2 = -FLT_MAX;
    #pragma unroll
    for (int t = 0; t < 16; t++) if (jbase + t <= lim) m2 = fmaxf(m2, s2[t]);
    m2 = warp_max(m2);

    float a[16]; float sum2 = 0.f;
    #pragma unroll
    for (int t = 0; t < 16; t++){
        a[t] = (jbase + t <= lim) ? __expf(s2[t] - m2) : 0.f;
        sum2 += a[t];
    }
    sum2 = warp_sum(sum2);
    float inv2 = (sum2 > 0.f) ? 1.f / sum2 : 0.f;
    if (!maskflag && i == 0) inv2 = 0.f;

    if (act){
        __nv_bfloat162 hp[8], lp[8];
        #pragma unroll
        for (int t = 0; t < 8; t++)
            split2(a[2*t] * inv2, a[2*t+1] * inv2, hp[t], lp[t]);
        bf16* pr = ph + (size_t)warp * Sn + jbase;
        bf16* lr = pl + (size_t)warp * Sn + jbase;
        *(uint4*)pr       = *(uint4*)&hp[0];
        *(uint4*)(pr + 8) = *(uint4*)&hp[4];
        *(uint4*)lr       = *(uint4*)&lp[0];
        *(uint4*)(lr + 8) = *(uint4*)&lp[4];
    }
}

// ---------------- residual + LayerNorm (+ bf16 split out) -------------------
__global__ __launch_bounds__(256)
void add_ln(const float* __restrict__ base, const float* __restrict__ delta,
            const float* __restrict__ g, const float* __restrict__ bt,
            float* __restrict__ out, bf16* __restrict__ oh, bf16* __restrict__ ol)
{
    long row = blockIdx.x;
    const float* x  = base  + row*Dn;
    const float* dl = delta + row*Dn;
    int t = threadIdx.x;
    __shared__ float red[32];

    float v0 = x[t]       + dl[t];
    float v1 = x[t + 256] + dl[t + 256];
    float s  = block_sum(v0 + v1, red);
    float sq = block_sum(v0*v0 + v1*v1, red);
    float mu  = s * (1.f/Dn);
    float var = sq * (1.f/Dn) - mu*mu;
    float inv = rsqrtf(var + 1e-5f);
    float o0 = (v0 - mu)*inv*g[t]       + bt[t];
    float o1 = (v1 - mu)*inv*g[t + 256] + bt[t + 256];
    out[row*Dn + t]       = o0;
    out[row*Dn + t + 256] = o1;
    bf16 h0 = __float2bfloat16(o0), h1 = __float2bfloat16(o1);
    oh[row*Dn + t]       = h0;
    oh[row*Dn + t + 256] = h1;
    ol[row*Dn + t]       = __float2bfloat16(o0 - __bfloat162float(h0));
    ol[row*Dn + t + 256] = __float2bfloat16(o1 - __bfloat162float(h1));
}

// ---------------- fp32 -> bf16 split ----------------------------------------
__global__ __launch_bounds__(256)
void k_split(const float* __restrict__ x, bf16* __restrict__ h,
             bf16* __restrict__ l, int n4)
{
    int i = blockIdx.x * blockDim.x + threadIdx.x;
    if (i >= n4) return;
    float4 v = ((const float4*)x)[i];
    __nv_bfloat162 hp0, hp1, lp0, lp1;
    split2(v.x, v.y, hp0, lp0);
    split2(v.z, v.w, hp1, lp1);
    ((__nv_bfloat162*)h)[2*i]   = hp0;
    ((__nv_bfloat162*)h)[2*i+1] = hp1;
    ((__nv_bfloat162*)l)[2*i]   = lp0;
    ((__nv_bfloat162*)l)[2*i+1] = lp1;
}

// ---------------- fp32 W[K,N] -> split bf16 W^T[N,K], batched over layers ---
__global__ __launch_bounds__(256)
void k_splitT(const float* __restrict__ W, bf16* __restrict__ hT,
              bf16* __restrict__ lT, int K, int N)
{
    size_t zoff = (size_t)blockIdx.z * K * N;
    W  += zoff; hT += zoff; lT += zoff;
    __shared__ float tile[32][33];
    int n0 = blockIdx.x * 32, k0 = blockIdx.y * 32;
    int tx = threadIdx.x & 31, ty = threadIdx.x >> 5;   // (32,8)
    #pragma unroll
    for (int i = 0; i < 32; i += 8)
        tile[ty+i][tx] = W[(size_t)(k0+ty+i)*N + n0+tx];
    __syncthreads();
    #pragma unroll
    for (int i = 0; i < 32; i += 8){
        float v = tile[tx][ty+i];
        size_t o = (size_t)(n0+ty+i)*K + k0+tx;
        bf16 h = __float2bfloat16(v);
        hT[o] = h;
        lT[o] = __float2bfloat16(v - __bfloat162float(h));
    }
}

// batched over {Wk,Wv,Wo} x layers: grid.z in [0, 3*Ln)
__global__ __launch_bounds__(256)
void k_splitT_qkv(const float* __restrict__ Wk, const float* __restrict__ Wv,
                  const float* __restrict__ Wo,
                  bf16* __restrict__ kh, bf16* __restrict__ kl,
                  bf16* __restrict__ vh, bf16* __restrict__ vl,
                  bf16* __restrict__ oh, bf16* __restrict__ ol)
{
    int which = blockIdx.z / Ln, l = blockIdx.z % Ln;
    size_t zoff = (size_t)l * Dn * Dn;
    const float* W = (which == 0 ? Wk : which == 1 ? Wv : Wo) + zoff;
    bf16* hT = (which == 0 ? kh : which == 1 ? vh : oh) + zoff;
    bf16* lT = (which == 0 ? kl : which == 1 ? vl : ol) + zoff;
    __shared__ float tile[32][33];
    int n0 = blockIdx.x * 32, k0 = blockIdx.y * 32;
    int tx = threadIdx.x & 31, ty = threadIdx.x >> 5;
    #pragma unroll
    for (int i = 0; i < 32; i += 8)
        tile[ty+i][tx] = W[(size_t)(k0+ty+i)*Dn + n0+tx];
    __syncthreads();
    #pragma unroll
    for (int i = 0; i < 32; i += 8){
        float v = tile[tx][ty+i];
        size_t o = (size_t)(n0+ty+i)*Dn + k0+tx;
        bf16 h = __float2bfloat16(v);
        hT[o] = h;
        lT[o] = __float2bfloat16(v - __bfloat162float(h));
    }
}

// ---------------- host orchestration ----------------------------------------
static float* sym_addr(const void* s){
    void* p = nullptr;
    cudaGetSymbolAddress(&p, s);
    return (float*)p;
}
static bf16* sym_addr_b(const void* s){
    void* p = nullptr;
    cudaGetSymbolAddress(&p, s);
    return (bf16*)p;
}

extern "C" void kernel_launch(void* const* d_in, const int* in_sizes, int n_in,
                              void* d_out, int out_size)
{
    (void)in_sizes; (void)n_in; (void)out_size;
    const float* q_embed  = (const float*)d_in[0];
    const float* qa_embed = (const float*)d_in[1];
    const float* Wk    = (const float*)d_in[3];
    const float* bk    = (const float*)d_in[4];
    const float* Wv    = (const float*)d_in[5];
    const float* bv    = (const float*)d_in[6];
    const float* Wo    = (const float*)d_in[7];
    const float* bo    = (const float*)d_in[8];
    const float* gam   = (const float*)d_in[9];
    const float* ln1g  = (const float*)d_in[10];
    const float* ln1b  = (const float*)d_in[11];
    const float* W1    = (const float*)d_in[12];
    const float* b1    = (const float*)d_in[13];
    const float* W2    = (const float*)d_in[14];
    const float* b2    = (const float*)d_in[15];
    const float* ln2g  = (const float*)d_in[16];
    const float* ln2b  = (const float*)d_in[17];

    float* x   = sym_addr(g_x);
    float* y   = sym_addr(g_y);
    float* tmp = sym_addr(g_tmp);
    float* sc  = sym_addr(g_sc);
    bf16 *xh=sym_addr_b(g_xh), *xl=sym_addr_b(g_xl);
    bf16 *yh=sym_addr_b(g_yh), *yl=sym_addr_b(g_yl);
    bf16 *qkh=sym_addr_b(g_qkh), *qkl=sym_addr_b(g_qkl);
    bf16 *vph=sym_addr_b(g_vph), *vpl=sym_addr_b(g_vpl);
    bf16 *ah=sym_addr_b(g_ah), *al=sym_addr_b(g_al);
    bf16 *fh=sym_addr_b(g_fh), *fl=sym_addr_b(g_fl);
    bf16 *ph=sym_addr_b(g_ph), *pl=sym_addr_b(g_pl);
    bf16 *wkh=sym_addr_b(g_wkh), *wkl=sym_addr_b(g_wkl);
    bf16 *wvh=sym_addr_b(g_wvh), *wvl=sym_addr_b(g_wvl);
    bf16 *woh=sym_addr_b(g_woh), *wol=sym_addr_b(g_wol);
    bf16 *w1h=sym_addr_b(g_w1h), *w1l=sym_addr_b(g_w1l);
    bf16 *w2h=sym_addr_b(g_w2h), *w2l=sym_addr_b(g_w2l);

    cudaFuncSetAttribute(hgemm<false,false,true>,
        cudaFuncAttributeMaxDynamicSharedMemorySize, HG_SMEM);
    cudaFuncSetAttribute(hgemm<true,true,false>,
        cudaFuncAttributeMaxDynamicSharedMemorySize, HG_SMEM);
    cudaFuncSetAttribute(hgemm_proj,
        cudaFuncAttributeMaxDynamicSharedMemorySize, HG_SMEM);
    cudaFuncSetAttribute(qk_hmma,
        cudaFuncAttributeMaxDynamicSharedMemorySize, QK_SMEM);
    cudaFuncSetAttribute(av_hmma,
        cudaFuncAttributeMaxDynamicSharedMemorySize, AV_SMEM);

    const size_t embBytes = (size_t)BSn*Dn*sizeof(float);
    cudaMemcpyAsync(x, q_embed,  embBytes, cudaMemcpyDeviceToDevice, 0);
    cudaMemcpyAsync(y, qa_embed, embBytes, cudaMemcpyDeviceToDevice, 0);

    // preprocessing: 5 kernel launches total
    k_splitT_qkv<<<dim3(Dn/32, Dn/32, 3*Ln), 256>>>(Wk, Wv, Wo,
        wkh, wkl, wvh, wvl, woh, wol);
    k_splitT<<<dim3(DFFn/32, Dn/32,  Ln), 256>>>(W1, w1h, w1l, Dn,   DFFn);
    k_splitT<<<dim3(Dn/32,  DFFn/32, Ln), 256>>>(W2, w2h, w2l, DFFn, Dn);
    k_split<<<(BSn*Dn/4+255)/256,256>>>(x, xh, xl, BSn*Dn/4);
    k_split<<<(BSn*Dn/4+255)/256,256>>>(y, yh, yl, BSn*Dn/4);

    auto tgM = [&](const bf16*Ah,const bf16*Al,const bf16*Bh,const bf16*Bl,
                   const float*bias, float*C, int N, int K){
        hgemm<false,false,true><<<dim3(N/128, BSn/128), 256, HG_SMEM>>>(
            Ah,Al,Bh,Bl,bias,C,nullptr,nullptr,N,K);
    };
    auto tgRelu = [&](const bf16*Ah,const bf16*Al,const bf16*Bh,const bf16*Bl,
                      const float*bias, bf16*Ch, bf16*Cl, int N, int K){
        hgemm<true,true,false><<<dim3(N/128, BSn/128), 256, HG_SMEM>>>(
            Ah,Al,Bh,Bl,bias,nullptr,Ch,Cl,N,K);
    };

    auto layer = [&](int l, float* q, bf16* qh, bf16* ql,
                     const bf16* vsh, const bf16* vsl, int maskflag, bool pos){
        long oD = (long)l*Dn*Dn, oF = (long)l*Dn*DFFn;
        // merged Q/K + V projections (pointer-select, single body)
        hgemm_proj<<<dim3(Dn/128, BSn/128, 2), 256, HG_SMEM>>>(
            qh,  ql,  wkh+oD, wkl+oD, bk + (long)l*Dn, qkh, qkl,
            vsh, vsl, wvh+oD, wvl+oD, bv + (long)l*Dn, vph, vpl, Dn, Dn);

        qk_hmma<<<dim3(4, 4, Bn*Hn), 256, QK_SMEM>>>(qkh, qkl, sc);
        attn_row<<<dim3(Bn*Hn*Sn/8, 1, 1), 256>>>(sc, ph, pl,
                                                  gam + (long)l*Hn, maskflag);
        av_hmma<<<dim3(4, Bn*Hn), 256, AV_SMEM>>>(ph, pl, vph, vpl, ah, al);

        tgM(ah, al, woh+oD, wol+oD, bo + (long)l*Dn, tmp, Dn, Dn);
        add_ln<<<BSn,256>>>(q, tmp, ln1g + (long)l*Dn, ln1b + (long)l*Dn, q, qh, ql);

        if (pos){
            tgRelu(qh, ql, w1h+oF, w1l+oF, b1 + (long)l*DFFn, fh, fl, DFFn, Dn);
            tgM(fh, fl, w2h+oF, w2l+oF, b2 + (long)l*Dn, tmp, Dn, DFFn);
            add_ln<<<BSn,256>>>(q, tmp, ln2g + (long)l*Dn, ln2b + (long)l*Dn, q, qh, ql);
        }
    };

    // blocks_1: self-attn on y, mask=1, FFN
    layer(0, y, yh, yl, yh, yl, 1, true);
    layer(1, y, yh, yl, yh, yl, 1, true);
    // blocks_2: (mask=1, no FFN) then (mask=0, values=y, FFN)
    layer(2, x, xh, xl, xh, xl, 1, false);
    layer(3, x, xh, xl, yh, yl, 0, true);
    layer(4, x, xh, xl, xh, xl, 1, false);
    layer(5, x, xh, xl, yh, yl, 0, true);

    cudaMemcpyAsync(d_out, x, embBytes, cudaMemcpyDeviceToDevice, 0);
    cudaMemcpyAsync((char*)d_out + embBytes, y, embBytes, cudaMemcpyDeviceToDevice, 0);
}

// round 15
// speedup vs baseline: 1.0114x; 1.0114x over previous
#include <cuda_runtime.h>
#include <cuda_bf16.h>
#include <math.h>
#include <float.h>
#include <stdint.h>

constexpr int Bn   = 16;
constexpr int Sn   = 512;
constexpr int Dn   = 512;
constexpr int Hn   = 8;
constexpr int DKn  = 64;
constexpr int DFFn = 2048;
constexpr int BSn  = Bn * Sn;          // 8192 rows
constexpr int Ln   = 6;

typedef __nv_bfloat16 bf16;

// ---------------- fp32 scratch ----------------
__device__ float g_x  [BSn*Dn];
__device__ float g_y  [BSn*Dn];
__device__ float g_tmp[BSn*Dn];
__device__ float g_sc [(size_t)Bn*Hn*Sn*Sn];   // 128 MB scores

// ---------------- bf16 split scratch ----------------
__device__ __align__(128) bf16 g_xh[BSn*Dn],  g_xl[BSn*Dn];
__device__ __align__(128) bf16 g_yh[BSn*Dn],  g_yl[BSn*Dn];
__device__ __align__(128) bf16 g_qkh[BSn*Dn], g_qkl[BSn*Dn];
__device__ __align__(128) bf16 g_vph[BSn*Dn], g_vpl[BSn*Dn];
__device__ __align__(128) bf16 g_ah[BSn*Dn],  g_al[BSn*Dn];
__device__ __align__(128) bf16 g_fh[BSn*DFFn],g_fl[BSn*DFFn];
__device__ __align__(128) bf16 g_ph[(size_t)Bn*Hn*Sn*Sn];   // probs hi
__device__ __align__(128) bf16 g_pl[(size_t)Bn*Hn*Sn*Sn];   // probs lo
// transposed split weights: [N,K] row-major
__device__ __align__(128) bf16 g_wkh[Ln*Dn*Dn],   g_wkl[Ln*Dn*Dn];
__device__ __align__(128) bf16 g_wvh[Ln*Dn*Dn],   g_wvl[Ln*Dn*Dn];
__device__ __align__(128) bf16 g_woh[Ln*Dn*Dn],   g_wol[Ln*Dn*Dn];
__device__ __align__(128) bf16 g_w1h[Ln*Dn*DFFn], g_w1l[Ln*Dn*DFFn];
__device__ __align__(128) bf16 g_w2h[Ln*DFFn*Dn], g_w2l[Ln*DFFn*Dn];

// ---------------- low-level helpers ----------------
__device__ __forceinline__ uint32_t smem_u32(const void* p){
    return (uint32_t)__cvta_generic_to_shared(p);
}
__device__ __forceinline__ void cp16(uint32_t dst, const void* src){
    asm volatile("cp.async.cg.shared.global [%0], [%1], 16;"
                 :: "r"(dst), "l"(src));
}
__device__ __forceinline__ void cp_commit(){
    asm volatile("cp.async.commit_group;" ::: "memory");
}
__device__ __forceinline__ void cp_wait0(){
    asm volatile("cp.async.wait_group 0;" ::: "memory");
}
__device__ __forceinline__ void ldm_x4(uint32_t* r, uint32_t addr){
    asm volatile("ldmatrix.sync.aligned.m8n8.x4.shared.b16 {%0,%1,%2,%3}, [%4];"
                 : "=r"(r[0]),"=r"(r[1]),"=r"(r[2]),"=r"(r[3]) : "r"(addr));
}
__device__ __forceinline__ void ldm_x4_t(uint32_t* r, uint32_t addr){
    asm volatile("ldmatrix.sync.aligned.m8n8.x4.trans.shared.b16 {%0,%1,%2,%3}, [%4];"
                 : "=r"(r[0]),"=r"(r[1]),"=r"(r[2]),"=r"(r[3]) : "r"(addr));
}
__device__ __forceinline__ void mma_bf16(float* c, const uint32_t* a,
                                         const uint32_t* b){
    asm volatile("mma.sync.aligned.m16n8k16.row.col.f32.bf16.bf16.f32 "
        "{%0,%1,%2,%3}, {%4,%5,%6,%7}, {%8,%9}, {%0,%1,%2,%3};"
        : "+f"(c[0]),"+f"(c[1]),"+f"(c[2]),"+f"(c[3])
        : "r"(a[0]),"r"(a[1]),"r"(a[2]),"r"(a[3]), "r"(b[0]),"r"(b[1]));
}
__device__ __forceinline__ void split2(float v0, float v1,
                                       __nv_bfloat162& hp, __nv_bfloat162& lp){
    bf16 h0 = __float2bfloat16(v0), h1 = __float2bfloat16(v1);
    hp.x = h0; hp.y = h1;
    lp.x = __float2bfloat16(v0 - __bfloat162float(h0));
    lp.y = __float2bfloat16(v1 - __bfloat162float(h1));
}
__device__ __forceinline__ float warp_sum(float v){
    #pragma unroll
    for (int o = 16; o > 0; o >>= 1) v += __shfl_xor_sync(0xffffffffu, v, o);
    return v;
}
__device__ __forceinline__ float warp_max(float v){
    #pragma unroll
    for (int o = 16; o > 0; o >>= 1) v = fmaxf(v, __shfl_xor_sync(0xffffffffu, v, o));
    return v;
}
__device__ __forceinline__ float block_sum(float v, float* red){
    int lane = threadIdx.x & 31, w = threadIdx.x >> 5, nw = blockDim.x >> 5;
    v = warp_sum(v);
    if (lane == 0) red[w] = v;
    __syncthreads();
    if (w == 0){
        float r = (lane < nw) ? red[lane] : 0.f;
        r = warp_sum(r);
        if (lane == 0) red[0] = r;
    }
    __syncthreads();
    float out = red[0];
    __syncthreads();
    return out;
}

constexpr int HG_STAGE = 32768;              // A(16K)+B(16K) per stage
constexpr int HG_SMEM  = 2*HG_STAGE;         // 64 KB dynamic (2-stage)
constexpr int AV_STAGE = 24576;              // P(16K)+V(8K)
constexpr int AV_SMEM  = 2*AV_STAGE;         // 48 KB
constexpr int QK_SMEM  = 65536;              // Ah,Al,Bh,Bl 16K each

// ---------------- HMMA split-bf16 GEMM body (2-stage, R12-identical) --------
// C[M,N] = A[M,K] @ B^T (B stored [N,K]); 3 passes Ah*Bh+Ah*Bl+Al*Bh.
template<bool RELU, bool SPLIT, bool WF32>
__device__ __forceinline__ void hgemm_body(
    const bf16* __restrict__ Ah, const bf16* __restrict__ Al,
    const bf16* __restrict__ Bh, const bf16* __restrict__ Bl,
    const float* __restrict__ bias, float* __restrict__ C,
    bf16* __restrict__ Ch, bf16* __restrict__ Cl, int N, int K)
{
    extern __shared__ char smem[];
    uint32_t sb = smem_u32(smem);
    int tid = threadIdx.x, lane = tid & 31, wid = tid >> 5;
    int wm = (wid >> 2) * 64, wn = (wid & 3) * 32;
    int n0 = blockIdx.x * 128, m0 = blockIdx.y * 128;

    const int CH = K >> 6;
    const int T  = 3 * CH;

    float acc[4][4][4];
    #pragma unroll
    for (int i = 0; i < 4; i++)
        #pragma unroll
        for (int j = 0; j < 4; j++)
            #pragma unroll
            for (int q = 0; q < 4; q++) acc[i][j][q] = 0.f;

    auto preload = [&](int t){
        int p = t / CH, c = t % CH, k0 = c << 6;
        const bf16* Asrc = (p < 2)  ? Ah : Al;
        const bf16* Bsrc = (p == 1) ? Bl : Bh;
        uint32_t buf = sb + (t & 1) * HG_STAGE;
        #pragma unroll
        for (int g = tid; g < 1024; g += 256){
            int r = g >> 3, ch = g & 7;
            cp16(buf + (r << 7) + ((ch ^ (r & 7)) << 4),
                 Asrc + (size_t)(m0 + r) * K + k0 + ch * 8);
        }
        #pragma unroll
        for (int g = tid; g < 1024; g += 256){
            int r = g >> 3, ch = g & 7;
            cp16(buf + 16384 + (r << 7) + ((ch ^ (r & 7)) << 4),
                 Bsrc + (size_t)(n0 + r) * K + k0 + ch * 8);
        }
        cp_commit();
    };

    preload(0);
    for (int t = 0; t < T; t++){
        cp_wait0();
        __syncthreads();
        if (t + 1 < T) preload(t + 1);

        uint32_t abuf = sb + (t & 1) * HG_STAGE;
        uint32_t bbuf = abuf + 16384;
        #pragma unroll
        for (int kk = 0; kk < 4; kk++){
            uint32_t af[4][4];
            #pragma unroll
            for (int mt = 0; mt < 4; mt++){
                int m = wm + mt*16 + (lane & 7) + ((lane >> 3) & 1) * 8;
                int kc = kk*2 + (lane >> 4);
                ldm_x4(af[mt], abuf + (m << 7) + ((kc ^ (m & 7)) << 4));
            }
            uint32_t bfr[2][4];
            #pragma unroll
            for (int pr = 0; pr < 2; pr++){
                int n = wn + pr*16 + (lane & 7) + (lane >> 4) * 8;
                int kc = kk*2 + ((lane >> 3) & 1);
                ldm_x4(bfr[pr], bbuf + (n << 7) + ((kc ^ (n & 7)) << 4));
            }
            #pragma unroll
            for (int mt = 0; mt < 4; mt++)
                #pragma unroll
                for (int nt = 0; nt < 4; nt++)
                    mma_bf16(acc[mt][nt], af[mt], &bfr[nt >> 1][(nt & 1) * 2]);
        }
        __syncthreads();
    }

    int qrow = lane >> 2, qcol = (lane & 3) * 2;
    #pragma unroll
    for (int mt = 0; mt < 4; mt++){
        #pragma unroll
        for (int nt = 0; nt < 4; nt++){
            int m = m0 + wm + mt*16 + qrow;
            int n = n0 + wn + nt*8 + qcol;
            float b0 = bias[n], b1 = bias[n+1];
            #pragma unroll
            for (int half = 0; half < 2; half++){
                int mm = m + half*8;
                float v0 = acc[mt][nt][half*2]   + b0;
                float v1 = acc[mt][nt][half*2+1] + b1;
                if (RELU){ v0 = fmaxf(v0, 0.f); v1 = fmaxf(v1, 0.f); }
                if (WF32){
                    float2 fv; fv.x = v0; fv.y = v1;
                    *(float2*)(C + (size_t)mm*N + n) = fv;
                }
                if (SPLIT){
                    __nv_bfloat162 hp, lp;
                    split2(v0, v1, hp, lp);
                    *(__nv_bfloat162*)(Ch + (size_t)mm*N + n) = hp;
                    *(__nv_bfloat162*)(Cl + (size_t)mm*N + n) = lp;
                }
            }
        }
    }
}

template<bool RELU, bool SPLIT, bool WF32>
__global__ void __launch_bounds__(256) hgemm(
    const bf16* __restrict__ Ah, const bf16* __restrict__ Al,
    const bf16* __restrict__ Bh, const bf16* __restrict__ Bl,
    const float* __restrict__ bias, float* __restrict__ C,
    bf16* __restrict__ Ch, bf16* __restrict__ Cl, int N, int K)
{
    hgemm_body<RELU,SPLIT,WF32>(Ah,Al,Bh,Bl,bias,C,Ch,Cl,N,K);
}

// merged Q/K + V projections: POINTER select by z, single body call.
__global__ void __launch_bounds__(256) hgemm_proj(
    const bf16* __restrict__ A0h, const bf16* __restrict__ A0l,
    const bf16* __restrict__ B0h, const bf16* __restrict__ B0l,
    const float* __restrict__ bias0, bf16* __restrict__ C0h, bf16* __restrict__ C0l,
    const bf16* __restrict__ A1h, const bf16* __restrict__ A1l,
    const bf16* __restrict__ B1h, const bf16* __restrict__ B1l,
    const float* __restrict__ bias1, bf16* __restrict__ C1h, bf16* __restrict__ C1l,
    int N, int K)
{
    bool z = (blockIdx.z != 0);
    const bf16* Ah = z ? A1h : A0h;
    const bf16* Al = z ? A1l : A0l;
    const bf16* Bh = z ? B1h : B0h;
    const bf16* Bl = z ? B1l : B0l;
    const float* bias = z ? bias1 : bias0;
    bf16* Ch = z ? C1h : C0h;
    bf16* Cl = z ? C1l : C0l;
    hgemm_body<false,true,false>(Ah,Al,Bh,Bl,bias,nullptr,Ch,Cl,N,K);
}

// ---------------- QK^T via HMMA: 128x128 tiles, K=64, triangular skip -------
__global__ void __launch_bounds__(256) qk_hmma(
    const bf16* __restrict__ qkh, const bf16* __restrict__ qkl,
    float* __restrict__ sc)
{
    int jt = blockIdx.x, it = blockIdx.y;
    if (jt > it) return;
    int bh = blockIdx.z, b = bh >> 3, h = bh & 7;
    int i0 = it * 128, j0 = jt * 128;

    extern __shared__ char smem[];
    uint32_t sb = smem_u32(smem);
    int tid = threadIdx.x, lane = tid & 31, wid = tid >> 5;

    const bf16* bh_ = qkh + (size_t)b*Sn*Dn + h*DKn;
    const bf16* bl_ = qkl + (size_t)b*Sn*Dn + h*DKn;
    for (int g = tid; g < 1024; g += 256){
        int r = g >> 3, ch = g & 7;
        uint32_t sw = (r << 7) + ((ch ^ (r & 7)) << 4);
        cp16(sb +         sw, bh_ + (size_t)(i0+r)*Dn + ch*8);
        cp16(sb + 16384 + sw, bl_ + (size_t)(i0+r)*Dn + ch*8);
        cp16(sb + 32768 + sw, bh_ + (size_t)(j0+r)*Dn + ch*8);
        cp16(sb + 49152 + sw, bl_ + (size_t)(j0+r)*Dn + ch*8);
    }
    cp_commit(); cp_wait0();
    __syncthreads();

    int wm = (wid >> 2) * 64, wn = (wid & 3) * 32;
    float acc[4][4][4];
    #pragma unroll
    for (int i = 0; i < 4; i++)
        #pragma unroll
        for (int j = 0; j < 4; j++)
            #pragma unroll
            for (int q = 0; q < 4; q++) acc[i][j][q] = 0.f;

    #pragma unroll
    for (int p = 0; p < 3; p++){
        uint32_t abuf = sb + ((p < 2) ? 0 : 16384);
        uint32_t bbuf = sb + 32768 + ((p == 1) ? 16384 : 0);
        #pragma unroll
        for (int kk = 0; kk < 4; kk++){
            uint32_t af[4][4];
            #pragma unroll
            for (int mt = 0; mt < 4; mt++){
                int m = wm + mt*16 + (lane & 7) + ((lane >> 3) & 1) * 8;
                int kc = kk*2 + (lane >> 4);
                ldm_x4(af[mt], abuf + (m << 7) + ((kc ^ (m & 7)) << 4));
            }
            uint32_t bfr[2][4];
            #pragma unroll
            for (int pr = 0; pr < 2; pr++){
                int n = wn + pr*16 + (lane & 7) + (lane >> 4) * 8;
                int kc = kk*2 + ((lane >> 3) & 1);
                ldm_x4(bfr[pr], bbuf + (n << 7) + ((kc ^ (n & 7)) << 4));
            }
            #pragma unroll
            for (int mt = 0; mt < 4; mt++)
                #pragma unroll
                for (int nt = 0; nt < 4; nt++)
                    mma_bf16(acc[mt][nt], af[mt], &bfr[nt >> 1][(nt & 1) * 2]);
        }
    }

    float* out = sc + (size_t)bh * Sn * Sn;
    int qrow = lane >> 2, qcol = (lane & 3) * 2;
    #pragma unroll
    for (int mt = 0; mt < 4; mt++)
        #pragma unroll
        for (int nt = 0; nt < 4; nt++)
            #pragma unroll
            for (int half = 0; half < 2; half++){
                int i = i0 + wm + mt*16 + qrow + half*8;
                int j = j0 + wn + nt*8 + qcol;
                float2 fv;
                fv.x = acc[mt][nt][half*2]   * 0.125f;
                fv.y = acc[mt][nt][half*2+1] * 0.125f;
                *(float2*)(out + (size_t)i*Sn + j) = fv;
            }
}

// ---------------- attn@V via HMMA (split probs x split V, trans-B) ----------
__global__ void __launch_bounds__(256) av_hmma(
    const bf16* __restrict__ ph, const bf16* __restrict__ pl,
    const bf16* __restrict__ vh, const bf16* __restrict__ vl,
    bf16* __restrict__ ah, bf16* __restrict__ al)
{
    int it = gridDim.x - 1 - blockIdx.x;     // big tiles scheduled first
    int bh = blockIdx.y, b = bh >> 3, h = bh & 7;
    int i0 = it * 128;

    extern __shared__ char smem[];
    uint32_t sb = smem_u32(smem);
    int tid = threadIdx.x, lane = tid & 31, wid = tid >> 5;

    const bf16* Ph = ph + (size_t)bh * Sn * Sn;
    const bf16* Pl = pl + (size_t)bh * Sn * Sn;
    const bf16* Vh = vh + (size_t)b*Sn*Dn + h*DKn;
    const bf16* Vl = vl + (size_t)b*Sn*Dn + h*DKn;

    const int nch = (it + 1) * 2;   // 64-wide j chunks
    const int T = 3 * nch;

    float acc[2][4][4];
    #pragma unroll
    for (int i = 0; i < 2; i++)
        #pragma unroll
        for (int j = 0; j < 4; j++)
            #pragma unroll
            for (int q = 0; q < 4; q++) acc[i][j][q] = 0.f;

    auto preload = [&](int t){
        int p = t / nch, c = t % nch, j0 = c << 6;
        const bf16* Ps = (p < 2)  ? Ph : Pl;
        const bf16* Vs = (p == 1) ? Vl : Vh;
        uint32_t buf = sb + (t & 1) * AV_STAGE;
        #pragma unroll
        for (int g = tid; g < 1024; g += 256){
            int r = g >> 3, ch = g & 7;
            cp16(buf + (r << 7) + ((ch ^ (r & 7)) << 4),
                 Ps + (size_t)(i0 + r) * Sn + j0 + ch * 8);
        }
        #pragma unroll
        for (int g = tid; g < 512; g += 256){
            int r = g >> 3, ch = g & 7;
            cp16(buf + 16384 + (r << 7) + ((ch ^ (r & 7)) << 4),
                 Vs + (size_t)(j0 + r) * Dn + ch * 8);
        }
        cp_commit();
    };

    preload(0);
    int wm = (wid >> 1) * 32, wn = (wid & 1) * 32;
    for (int t = 0; t < T; t++){
        cp_wait0();
        __syncthreads();
        if (t + 1 < T) preload(t + 1);

        uint32_t pb = sb + (t & 1) * AV_STAGE;
        uint32_t vb = pb + 16384;
        #pragma unroll
        for (int kk = 0; kk < 4; kk++){
            uint32_t af[2][4];
            #pragma unroll
            for (int mt = 0; mt < 2; mt++){
                int m = wm + mt*16 + (lane & 7) + ((lane >> 3) & 1) * 8;
                int kc = kk*2 + (lane >> 4);
                ldm_x4(af[mt], pb + (m << 7) + ((kc ^ (m & 7)) << 4));
            }
            uint32_t bfr[2][4];
            #pragma unroll
            for (int ng = 0; ng < 2; ng++){
                int row  = kk*16 + (lane & 7) + ((lane >> 3) & 1) * 8;
                int ncol = wn + ng*16 + ((lane >> 4) & 1) * 8;
                ldm_x4_t(bfr[ng], vb + (row << 7) + (((ncol >> 3) ^ (row & 7)) << 4));
            }
            #pragma unroll
            for (int mt = 0; mt < 2; mt++)
                #pragma unroll
                for (int nt = 0; nt < 4; nt++)
                    mma_bf16(acc[mt][nt], af[mt], &bfr[nt >> 1][(nt & 1) * 2]);
        }
        __syncthreads();
    }

    int qrow = lane >> 2, qcol = (lane & 3) * 2;
    #pragma unroll
    for (int mt = 0; mt < 2; mt++)
        #pragma unroll
        for (int nt = 0; nt < 4; nt++)
            #pragma unroll
            for (int half = 0; half < 2; half++){
                int i = i0 + wm + mt*16 + qrow + half*8;
                int d = wn + nt*8 + qcol;
                size_t off = (size_t)(b*Sn + i) * Dn + h*DKn + d;
                __nv_bfloat162 hp, lp;
                split2(acc[mt][nt][half*2], acc[mt][nt][half*2+1], hp, lp);
                *(__nv_bfloat162*)(ah + off) = hp;
                *(__nv_bfloat162*)(al + off) = lp;
            }
}

// ---------------- fused attention row pass (warp per row) -------------------
__global__ __launch_bounds__(256)
void attn_row(const float* __restrict__ sc, bf16* __restrict__ ph,
              bf16* __restrict__ pl, const float* __restrict__ gamma,
              int maskflag)
{
    const unsigned FULL = 0xffffffffu;
    int warp = (blockIdx.x * blockDim.x + threadIdx.x) >> 5;
    int lane = threadIdx.x & 31;
    int i = warp & (Sn-1);
    int h = (warp >> 9) & (Hn-1);
    const float* row = sc + (size_t)warp * Sn;
    int jbase = lane * 16;
    int jlim = ((i >> 7) + 1) << 7;
    bool act = jbase < jlim;
    int lim = maskflag ? i : (i - 1);

    float s[16];
    if (act){
        #pragma unroll
        for (int q = 0; q < 4; q++)
            *(float4*)&s[q*4] = *(const float4*)(row + jbase + q*4);
    } else {
        #pragma unroll
        for (int t = 0; t < 16; t++) s[t] = 0.f;
    }

    float m = -FLT_MAX;
    #pragma unroll
    for (int t = 0; t < 16; t++) if (jbase + t <= lim) m = fmaxf(m, s[t]);
    m = warp_max(m);

    float e[16]; float sum = 0.f;
    #pragma unroll
    for (int t = 0; t < 16; t++){
        e[t] = (jbase + t <= lim) ? __expf(s[t] - m) : 0.f;
        sum += e[t];
    }
    sum = warp_sum(sum);
    float inv1 = (sum > 0.f) ? 1.f / sum : 0.f;

    float c[16]; float run = 0.f;
    #pragma unroll
    for (int t = 0; t < 16; t++){ run += e[t]; c[t] = run; }
    float incl = run;
    #pragma unroll
    for (int o = 1; o < 32; o <<= 1){
        float tsh = __shfl_up_sync(FULL, incl, o);
        if (lane >= o) incl += tsh;
    }
    float excl = incl - run;

    float gm = gamma[h];
    float sp = (gm > 20.f) ? gm : log1pf(__expf(gm));
    float fi = (float)i;

    float s2[16];
    #pragma unroll
    for (int t = 0; t < 16; t++){
        float cumincl = excl + c[t];
        float rem = fmaxf(sum - cumincl, 0.f) * inv1;
        float pos = fabsf(fi - (float)(jbase + t));
        float dist = sqrtf(rem * pos);
        float eff = fminf(fmaxf(__expf(-sp * dist), 1e-5f), 1e5f);
        s2[t] = s[t] * eff;
    }

    float m2 = -FLT_MAX;
    #pragma unroll
    for (int t = 0; t < 16; t++) if (jbase + t <= lim) m2 = fmaxf(m2, s2[t]);
    m2 = warp_max(m2);

    float a[16]; float sum2 = 0.f;
    #pragma unroll
    for (int t = 0; t < 16; t++){
        a[t] = (jbase + t <= lim) ? __expf(s2[t] - m2) : 0.f;
        sum2 += a[t];
    }
    sum2 = warp_sum(sum2);
    float inv2 = (sum2 > 0.f) ? 1.f / sum2 : 0.f;
    if (!maskflag && i == 0) inv2 = 0.f;

    if (act){
        __nv_bfloat162 hp[8], lp[8];
        #pragma unroll
        for (int t = 0; t < 8; t++)
            split2(a[2*t] * inv2, a[2*t+1] * inv2, hp[t], lp[t]);
        bf16* pr = ph + (size_t)warp * Sn + jbase;
        bf16* lr = pl + (size_t)warp * Sn + jbase;
        *(uint4*)pr       = *(uint4*)&hp[0];
        *(uint4*)(pr + 8) = *(uint4*)&hp[4];
        *(uint4*)lr       = *(uint4*)&lp[0];
        *(uint4*)(lr + 8) = *(uint4*)&lp[4];
    }
}

// ---------------- residual + LayerNorm (+ bf16 split out) -------------------
__global__ __launch_bounds__(256)
void add_ln(const float* __restrict__ base, const float* __restrict__ delta,
            const float* __restrict__ g, const float* __restrict__ bt,
            float* __restrict__ out, bf16* __restrict__ oh, bf16* __restrict__ ol)
{
    long row = blockIdx.x;
    const float* x  = base  + row*Dn;
    const float* dl = delta + row*Dn;
    int t = threadIdx.x;
    __shared__ float red[32];

    float v0 = x[t]       + dl[t];
    float v1 = x[t + 256] + dl[t + 256];
    float s  = block_sum(v0 + v1, red);
    float sq = block_sum(v0*v0 + v1*v1, red);
    float mu  = s * (1.f/Dn);
    float var = sq * (1.f/Dn) - mu*mu;
    float inv = rsqrtf(var + 1e-5f);
    float o0 = (v0 - mu)*inv*g[t]       + bt[t];
    float o1 = (v1 - mu)*inv*g[t + 256] + bt[t + 256];
    out[row*Dn + t]       = o0;
    out[row*Dn + t + 256] = o1;
    bf16 h0 = __float2bfloat16(o0), h1 = __float2bfloat16(o1);
    oh[row*Dn + t]       = h0;
    oh[row*Dn + t + 256] = h1;
    ol[row*Dn + t]       = __float2bfloat16(o0 - __bfloat162float(h0));
    ol[row*Dn + t + 256] = __float2bfloat16(o1 - __bfloat162float(h1));
}

// ---------------- fp32 -> bf16 split ----------------------------------------
__global__ __launch_bounds__(256)
void k_split(const float* __restrict__ x, bf16* __restrict__ h,
             bf16* __restrict__ l, int n4)
{
    int i = blockIdx.x * blockDim.x + threadIdx.x;
    if (i >= n4) return;
    float4 v = ((const float4*)x)[i];
    __nv_bfloat162 hp0, hp1, lp0, lp1;
    split2(v.x, v.y, hp0, lp0);
    split2(v.z, v.w, hp1, lp1);
    ((__nv_bfloat162*)h)[2*i]   = hp0;
    ((__nv_bfloat162*)h)[2*i+1] = hp1;
    ((__nv_bfloat162*)l)[2*i]   = lp0;
    ((__nv_bfloat162*)l)[2*i+1] = lp1;
}

// ---------------- fp32 W[K,N] -> split bf16 W^T[N,K], batched over layers ---
__global__ __launch_bounds__(256)
void k_splitT(const float* __restrict__ W, bf16* __restrict__ hT,
              bf16* __restrict__ lT, int K, int N)
{
    size_t zoff = (size_t)blockIdx.z * K * N;
    W  += zoff; hT += zoff; lT += zoff;
    __shared__ float tile[32][33];
    int n0 = blockIdx.x * 32, k0 = blockIdx.y * 32;
    int tx = threadIdx.x & 31, ty = threadIdx.x >> 5;   // (32,8)
    #pragma unroll
    for (int i = 0; i < 32; i += 8)
        tile[ty+i][tx] = W[(size_t)(k0+ty+i)*N + n0+tx];
    __syncthreads();
    #pragma unroll
    for (int i = 0; i < 32; i += 8){
        float v = tile[tx][ty+i];
        size_t o = (size_t)(n0+ty+i)*K + k0+tx;
        bf16 h = __float2bfloat16(v);
        hT[o] = h;
        lT[o] = __float2bfloat16(v - __bfloat162float(h));
    }
}

// batched over {Wk,Wv,Wo} x layers: grid.z in [0, 3*Ln)
__global__ __launch_bounds__(256)
void k_splitT_qkv(const float* __restrict__ Wk, const float* __restrict__ Wv,
                  const float* __restrict__ Wo,
                  bf16* __restrict__ kh, bf16* __restrict__ kl,
                  bf16* __restrict__ vh, bf16* __restrict__ vl,
                  bf16* __restrict__ oh, bf16* __restrict__ ol)
{
    int which = blockIdx.z / Ln, l = blockIdx.z % Ln;
    size_t zoff = (size_t)l * Dn * Dn;
    const float* W = (which == 0 ? Wk : which == 1 ? Wv : Wo) + zoff;
    bf16* hT = (which == 0 ? kh : which == 1 ? vh : oh) + zoff;
    bf16* lT = (which == 0 ? kl : which == 1 ? vl : ol) + zoff;
    __shared__ float tile[32][33];
    int n0 = blockIdx.x * 32, k0 = blockIdx.y * 32;
    int tx = threadIdx.x & 31, ty = threadIdx.x >> 5;
    #pragma unroll
    for (int i = 0; i < 32; i += 8)
        tile[ty+i][tx] = W[(size_t)(k0+ty+i)*Dn + n0+tx];
    __syncthreads();
    #pragma unroll
    for (int i = 0; i < 32; i += 8){
        float v = tile[tx][ty+i];
        size_t o = (size_t)(n0+ty+i)*Dn + k0+tx;
        bf16 h = __float2bfloat16(v);
        hT[o] = h;
        lT[o] = __float2bfloat16(v - __bfloat162float(h));
    }
}

// ---------------- host orchestration ----------------------------------------
static float* sym_addr(const void* s){
    void* p = nullptr;
    cudaGetSymbolAddress(&p, s);
    return (float*)p;
}
static bf16* sym_addr_b(const void* s){
    void* p = nullptr;
    cudaGetSymbolAddress(&p, s);
    return (bf16*)p;
}

extern "C" void kernel_launch(void* const* d_in, const int* in_sizes, int n_in,
                              void* d_out, int out_size)
{
    (void)in_sizes; (void)n_in; (void)out_size;
    const float* q_embed  = (const float*)d_in[0];
    const float* qa_embed = (const float*)d_in[1];
    const float* Wk    = (const float*)d_in[3];
    const float* bk    = (const float*)d_in[4];
    const float* Wv    = (const float*)d_in[5];
    const float* bv    = (const float*)d_in[6];
    const float* Wo    = (const float*)d_in[7];
    const float* bo    = (const float*)d_in[8];
    const float* gam   = (const float*)d_in[9];
    const float* ln1g  = (const float*)d_in[10];
    const float* ln1b  = (const float*)d_in[11];
    const float* W1    = (const float*)d_in[12];
    const float* b1    = (const float*)d_in[13];
    const float* W2    = (const float*)d_in[14];
    const float* b2    = (const float*)d_in[15];
    const float* ln2g  = (const float*)d_in[16];
    const float* ln2b  = (const float*)d_in[17];

    float* x   = sym_addr(g_x);
    float* y   = sym_addr(g_y);
    float* tmp = sym_addr(g_tmp);
    float* sc  = sym_addr(g_sc);
    bf16 *xh=sym_addr_b(g_xh), *xl=sym_addr_b(g_xl);
    bf16 *yh=sym_addr_b(g_yh), *yl=sym_addr_b(g_yl);
    bf16 *qkh=sym_addr_b(g_qkh), *qkl=sym_addr_b(g_qkl);
    bf16 *vph=sym_addr_b(g_vph), *vpl=sym_addr_b(g_vpl);
    bf16 *ah=sym_addr_b(g_ah), *al=sym_addr_b(g_al);
    bf16 *fh=sym_addr_b(g_fh), *fl=sym_addr_b(g_fl);
    bf16 *ph=sym_addr_b(g_ph), *pl=sym_addr_b(g_pl);
    bf16 *wkh=sym_addr_b(g_wkh), *wkl=sym_addr_b(g_wkl);
    bf16 *wvh=sym_addr_b(g_wvh), *wvl=sym_addr_b(g_wvl);
    bf16 *woh=sym_addr_b(g_woh), *wol=sym_addr_b(g_wol);
    bf16 *w1h=sym_addr_b(g_w1h), *w1l=sym_addr_b(g_w1l);
    bf16 *w2h=sym_addr_b(g_w2h), *w2l=sym_addr_b(g_w2l);

    cudaFuncSetAttribute(hgemm<false,false,true>,
        cudaFuncAttributeMaxDynamicSharedMemorySize, HG_SMEM);
    cudaFuncSetAttribute(hgemm<true,true,false>,
        cudaFuncAttributeMaxDynamicSharedMemorySize, HG_SMEM);
    cudaFuncSetAttribute(hgemm_proj,
        cudaFuncAttributeMaxDynamicSharedMemorySize, HG_SMEM);
    cudaFuncSetAttribute(qk_hmma,
        cudaFuncAttributeMaxDynamicSharedMemorySize, QK_SMEM);
    cudaFuncSetAttribute(av_hmma,
        cudaFuncAttributeMaxDynamicSharedMemorySize, AV_SMEM);

    const size_t embBytes = (size_t)BSn*Dn*sizeof(float);
    cudaMemcpyAsync(x, q_embed,  embBytes, cudaMemcpyDeviceToDevice, 0);
    cudaMemcpyAsync(y, qa_embed, embBytes, cudaMemcpyDeviceToDevice, 0);

    // preprocessing: 5 kernel launches total
    k_splitT_qkv<<<dim3(Dn/32, Dn/32, 3*Ln), 256>>>(Wk, Wv, Wo,
        wkh, wkl, wvh, wvl, woh, wol);
    k_splitT<<<dim3(DFFn/32, Dn/32,  Ln), 256>>>(W1, w1h, w1l, Dn,   DFFn);
    k_splitT<<<dim3(Dn/32,  DFFn/32, Ln), 256>>>(W2, w2h, w2l, DFFn, Dn);
    k_split<<<(BSn*Dn/4+255)/256,256>>>(x, xh, xl, BSn*Dn/4);
    k_split<<<(BSn*Dn/4+255)/256,256>>>(y, yh, yl, BSn*Dn/4);

    auto tgM = [&](const bf16*Ah,const bf16*Al,const bf16*Bh,const bf16*Bl,
                   const float*bias, float*C, int N, int K){
        hgemm<false,false,true><<<dim3(N/128, BSn/128), 256, HG_SMEM>>>(
            Ah,Al,Bh,Bl,bias,C,nullptr,nullptr,N,K);
    };
    auto tgRelu = [&](const bf16*Ah,const bf16*Al,const bf16*Bh,const bf16*Bl,
                      const float*bias, bf16*Ch, bf16*Cl, int N, int K){
        hgemm<true,true,false><<<dim3(N/128, BSn/128), 256, HG_SMEM>>>(
            Ah,Al,Bh,Bl,bias,nullptr,Ch,Cl,N,K);
    };

    auto layer = [&](int l, float* q, bf16* qh, bf16* ql,
                     const bf16* vsh, const bf16* vsl, int maskflag, bool pos){
        long oD = (long)l*Dn*Dn, oF = (long)l*Dn*DFFn;
        // merged Q/K + V projections (pointer-select, single body, 2-stage)
        hgemm_proj<<<dim3(Dn/128, BSn/128, 2), 256, HG_SMEM>>>(
            qh,  ql,  wkh+oD, wkl+oD, bk + (long)l*Dn, qkh, qkl,
            vsh, vsl, wvh+oD, wvl+oD, bv + (long)l*Dn, vph, vpl, Dn, Dn);

        qk_hmma<<<dim3(4, 4, Bn*Hn), 256, QK_SMEM>>>(qkh, qkl, sc);
        attn_row<<<dim3(Bn*Hn*Sn/8, 1, 1), 256>>>(sc, ph, pl,
                                                  gam + (long)l*Hn, maskflag);
        av_hmma<<<dim3(4, Bn*Hn), 256, AV_SMEM>>>(ph, pl, vph, vpl, ah, al);

        tgM(ah, al, woh+oD, wol+oD, bo + (long)l*Dn, tmp, Dn, Dn);
        add_ln<<<BSn,256>>>(q, tmp, ln1g + (long)l*Dn, ln1b + (long)l*Dn, q, qh, ql);

        if (pos){
            tgRelu(qh, ql, w1h+oF, w1l+oF, b1 + (long)l*DFFn, fh, fl, DFFn, Dn);
            tgM(fh, fl, w2h+oF, w2l+oF, b2 + (long)l*Dn, tmp, Dn, DFFn);
            add_ln<<<BSn,256>>>(q, tmp, ln2g + (long)l*Dn, ln2b + (long)l*Dn, q, qh, ql);
        }
    };

    // blocks_1: self-attn on y, mask=1, FFN
    layer(0, y, yh, yl, yh, yl, 1, true);
    layer(1, y, yh, yl, yh, yl, 1, true);
    // blocks_2: (mask=1, no FFN) then (mask=0, values=y, FFN)
    layer(2, x, xh, xl, xh, xl, 1, false);
    layer(3, x, xh, xl, yh, yl, 0, true);
    layer(4, x, xh, xl, xh, xl, 1, false);
    layer(5, x, xh, xl, yh, yl, 0, true);

    cudaMemcpyAsync(d_out, x, embBytes, cudaMemcpyDeviceToDevice, 0);
    cudaMemcpyAsync((char*)d_out + embBytes, y, embBytes, cudaMemcpyDeviceToDevice, 0);
}

// round 17
// speedup vs baseline: 1.0429x; 1.0311x over previous
#include <cuda_runtime.h>
#include <cuda_bf16.h>
#include <math.h>
#include <float.h>
#include <stdint.h>

constexpr int Bn   = 16;
constexpr int Sn   = 512;
constexpr int Dn   = 512;
constexpr int Hn   = 8;
constexpr int DKn  = 64;
constexpr int DFFn = 2048;
constexpr int BSn  = Bn * Sn;          // 8192 rows
constexpr int Ln   = 6;

typedef __nv_bfloat16 bf16;

// ---------------- fp32 scratch ----------------
__device__ float g_x  [BSn*Dn];
__device__ float g_y  [BSn*Dn];
__device__ float g_tmp[BSn*Dn];
__device__ float g_sc [(size_t)Bn*Hn*Sn*Sn];   // 128 MB scores

// ---------------- bf16 split scratch ----------------
__device__ __align__(128) bf16 g_xh[BSn*Dn],  g_xl[BSn*Dn];
__device__ __align__(128) bf16 g_yh[BSn*Dn],  g_yl[BSn*Dn];
__device__ __align__(128) bf16 g_qkh[BSn*Dn], g_qkl[BSn*Dn];
__device__ __align__(128) bf16 g_vph[BSn*Dn], g_vpl[BSn*Dn];
__device__ __align__(128) bf16 g_ah[BSn*Dn],  g_al[BSn*Dn];
__device__ __align__(128) bf16 g_fh[BSn*DFFn],g_fl[BSn*DFFn];
__device__ __align__(128) bf16 g_ph[(size_t)Bn*Hn*Sn*Sn];   // probs hi
__device__ __align__(128) bf16 g_pl[(size_t)Bn*Hn*Sn*Sn];   // probs lo
// transposed split weights: [N,K] row-major
__device__ __align__(128) bf16 g_wkh[Ln*Dn*Dn],   g_wkl[Ln*Dn*Dn];
__device__ __align__(128) bf16 g_wvh[Ln*Dn*Dn],   g_wvl[Ln*Dn*Dn];
__device__ __align__(128) bf16 g_woh[Ln*Dn*Dn],   g_wol[Ln*Dn*Dn];
__device__ __align__(128) bf16 g_w1h[Ln*Dn*DFFn], g_w1l[Ln*Dn*DFFn];
__device__ __align__(128) bf16 g_w2h[Ln*DFFn*Dn], g_w2l[Ln*DFFn*Dn];

// ---------------- low-level helpers ----------------
__device__ __forceinline__ uint32_t smem_u32(const void* p){
    return (uint32_t)__cvta_generic_to_shared(p);
}
__device__ __forceinline__ void cp16(uint32_t dst, const void* src){
    asm volatile("cp.async.cg.shared.global [%0], [%1], 16;"
                 :: "r"(dst), "l"(src));
}
__device__ __forceinline__ void cp_commit(){
    asm volatile("cp.async.commit_group;" ::: "memory");
}
__device__ __forceinline__ void cp_wait0(){
    asm volatile("cp.async.wait_group 0;" ::: "memory");
}
__device__ __forceinline__ void ldm_x4(uint32_t* r, uint32_t addr){
    asm volatile("ldmatrix.sync.aligned.m8n8.x4.shared.b16 {%0,%1,%2,%3}, [%4];"
                 : "=r"(r[0]),"=r"(r[1]),"=r"(r[2]),"=r"(r[3]) : "r"(addr));
}
__device__ __forceinline__ void ldm_x4_t(uint32_t* r, uint32_t addr){
    asm volatile("ldmatrix.sync.aligned.m8n8.x4.trans.shared.b16 {%0,%1,%2,%3}, [%4];"
                 : "=r"(r[0]),"=r"(r[1]),"=r"(r[2]),"=r"(r[3]) : "r"(addr));
}
__device__ __forceinline__ void mma_bf16(float* c, const uint32_t* a,
                                         const uint32_t* b){
    asm volatile("mma.sync.aligned.m16n8k16.row.col.f32.bf16.bf16.f32 "
        "{%0,%1,%2,%3}, {%4,%5,%6,%7}, {%8,%9}, {%0,%1,%2,%3};"
        : "+f"(c[0]),"+f"(c[1]),"+f"(c[2]),"+f"(c[3])
        : "r"(a[0]),"r"(a[1]),"r"(a[2]),"r"(a[3]), "r"(b[0]),"r"(b[1]));
}
__device__ __forceinline__ void split2(float v0, float v1,
                                       __nv_bfloat162& hp, __nv_bfloat162& lp){
    bf16 h0 = __float2bfloat16(v0), h1 = __float2bfloat16(v1);
    hp.x = h0; hp.y = h1;
    lp.x = __float2bfloat16(v0 - __bfloat162float(h0));
    lp.y = __float2bfloat16(v1 - __bfloat162float(h1));
}
__device__ __forceinline__ float warp_sum(float v){
    #pragma unroll
    for (int o = 16; o > 0; o >>= 1) v += __shfl_xor_sync(0xffffffffu, v, o);
    return v;
}
__device__ __forceinline__ float warp_max(float v){
    #pragma unroll
    for (int o = 16; o > 0; o >>= 1) v = fmaxf(v, __shfl_xor_sync(0xffffffffu, v, o));
    return v;
}
__device__ __forceinline__ float block_sum(float v, float* red){
    int lane = threadIdx.x & 31, w = threadIdx.x >> 5, nw = blockDim.x >> 5;
    v = warp_sum(v);
    if (lane == 0) red[w] = v;
    __syncthreads();
    if (w == 0){
        float r = (lane < nw) ? red[lane] : 0.f;
        r = warp_sum(r);
        if (lane == 0) red[0] = r;
    }
    __syncthreads();
    float out = red[0];
    __syncthreads();
    return out;
}

constexpr int HG_STAGE = 32768;              // A(16K)+B(16K) per stage
constexpr int HG_SMEM  = 2*HG_STAGE;         // 64 KB dynamic (2-stage)
constexpr int AV_STAGE = 24576;              // P(16K)+V(8K)
constexpr int AV_SMEM  = 2*AV_STAGE;         // 48 KB
constexpr int QK_SMEM  = 65536;              // Ah,Al,Bh,Bl 16K each

// ---------------- HMMA split-bf16 GEMM (dense projections/FFN) ---------------
// C[M,N] = A[M,K] @ B^T (B stored [N,K]); 3 passes Ah*Bh+Ah*Bl+Al*Bh.
template<bool RELU, bool SPLIT, bool WF32>
__global__ void __launch_bounds__(256) hgemm(
    const bf16* __restrict__ Ah, const bf16* __restrict__ Al,
    const bf16* __restrict__ Bh, const bf16* __restrict__ Bl,
    const float* __restrict__ bias, float* __restrict__ C,
    bf16* __restrict__ Ch, bf16* __restrict__ Cl, int N, int K)
{
    extern __shared__ char smem[];
    uint32_t sb = smem_u32(smem);
    int tid = threadIdx.x, lane = tid & 31, wid = tid >> 5;
    int wm = (wid >> 2) * 64, wn = (wid & 3) * 32;
    int n0 = blockIdx.x * 128, m0 = blockIdx.y * 128;

    const int CH = K >> 6;
    const int T  = 3 * CH;

    float acc[4][4][4];
    #pragma unroll
    for (int i = 0; i < 4; i++)
        #pragma unroll
        for (int j = 0; j < 4; j++)
            #pragma unroll
            for (int q = 0; q < 4; q++) acc[i][j][q] = 0.f;

    auto preload = [&](int t){
        int p = t / CH, c = t % CH, k0 = c << 6;
        const bf16* Asrc = (p < 2)  ? Ah : Al;
        const bf16* Bsrc = (p == 1) ? Bl : Bh;
        uint32_t buf = sb + (t & 1) * HG_STAGE;
        #pragma unroll
        for (int g = tid; g < 1024; g += 256){
            int r = g >> 3, ch = g & 7;
            cp16(buf + (r << 7) + ((ch ^ (r & 7)) << 4),
                 Asrc + (size_t)(m0 + r) * K + k0 + ch * 8);
        }
        #pragma unroll
        for (int g = tid; g < 1024; g += 256){
            int r = g >> 3, ch = g & 7;
            cp16(buf + 16384 + (r << 7) + ((ch ^ (r & 7)) << 4),
                 Bsrc + (size_t)(n0 + r) * K + k0 + ch * 8);
        }
        cp_commit();
    };

    preload(0);
    for (int t = 0; t < T; t++){
        cp_wait0();
        __syncthreads();
        if (t + 1 < T) preload(t + 1);

        uint32_t abuf = sb + (t & 1) * HG_STAGE;
        uint32_t bbuf = abuf + 16384;
        #pragma unroll
        for (int kk = 0; kk < 4; kk++){
            uint32_t af[4][4];
            #pragma unroll
            for (int mt = 0; mt < 4; mt++){
                int m = wm + mt*16 + (lane & 7) + ((lane >> 3) & 1) * 8;
                int kc = kk*2 + (lane >> 4);
                ldm_x4(af[mt], abuf + (m << 7) + ((kc ^ (m & 7)) << 4));
            }
            uint32_t bfr[2][4];
            #pragma unroll
            for (int pr = 0; pr < 2; pr++){
                int n = wn + pr*16 + (lane & 7) + (lane >> 4) * 8;
                int kc = kk*2 + ((lane >> 3) & 1);
                ldm_x4(bfr[pr], bbuf + (n << 7) + ((kc ^ (n & 7)) << 4));
            }
            #pragma unroll
            for (int mt = 0; mt < 4; mt++)
                #pragma unroll
                for (int nt = 0; nt < 4; nt++)
                    mma_bf16(acc[mt][nt], af[mt], &bfr[nt >> 1][(nt & 1) * 2]);
        }
        __syncthreads();
    }

    int qrow = lane >> 2, qcol = (lane & 3) * 2;
    #pragma unroll
    for (int mt = 0; mt < 4; mt++){
        #pragma unroll
        for (int nt = 0; nt < 4; nt++){
            int m = m0 + wm + mt*16 + qrow;
            int n = n0 + wn + nt*8 + qcol;
            float b0 = bias[n], b1 = bias[n+1];
            #pragma unroll
            for (int half = 0; half < 2; half++){
                int mm = m + half*8;
                float v0 = acc[mt][nt][half*2]   + b0;
                float v1 = acc[mt][nt][half*2+1] + b1;
                if (RELU){ v0 = fmaxf(v0, 0.f); v1 = fmaxf(v1, 0.f); }
                if (WF32){
                    float2 fv; fv.x = v0; fv.y = v1;
                    *(float2*)(C + (size_t)mm*N + n) = fv;
                }
                if (SPLIT){
                    __nv_bfloat162 hp, lp;
                    split2(v0, v1, hp, lp);
                    *(__nv_bfloat162*)(Ch + (size_t)mm*N + n) = hp;
                    *(__nv_bfloat162*)(Cl + (size_t)mm*N + n) = lp;
                }
            }
        }
    }
}

// ---------------- QK^T via HMMA: 128x128 tiles, K=64, triangular skip -------
__global__ void __launch_bounds__(256) qk_hmma(
    const bf16* __restrict__ qkh, const bf16* __restrict__ qkl,
    float* __restrict__ sc)
{
    int jt = blockIdx.x, it = blockIdx.y;
    if (jt > it) return;
    int bh = blockIdx.z, b = bh >> 3, h = bh & 7;
    int i0 = it * 128, j0 = jt * 128;

    extern __shared__ char smem[];
    uint32_t sb = smem_u32(smem);
    int tid = threadIdx.x, lane = tid & 31, wid = tid >> 5;

    const bf16* bh_ = qkh + (size_t)b*Sn*Dn + h*DKn;
    const bf16* bl_ = qkl + (size_t)b*Sn*Dn + h*DKn;
    for (int g = tid; g < 1024; g += 256){
        int r = g >> 3, ch = g & 7;
        uint32_t sw = (r << 7) + ((ch ^ (r & 7)) << 4);
        cp16(sb +         sw, bh_ + (size_t)(i0+r)*Dn + ch*8);
        cp16(sb + 16384 + sw, bl_ + (size_t)(i0+r)*Dn + ch*8);
        cp16(sb + 32768 + sw, bh_ + (size_t)(j0+r)*Dn + ch*8);
        cp16(sb + 49152 + sw, bl_ + (size_t)(j0+r)*Dn + ch*8);
    }
    cp_commit(); cp_wait0();
    __syncthreads();

    int wm = (wid >> 2) * 64, wn = (wid & 3) * 32;
    float acc[4][4][4];
    #pragma unroll
    for (int i = 0; i < 4; i++)
        #pragma unroll
        for (int j = 0; j < 4; j++)
            #pragma unroll
            for (int q = 0; q < 4; q++) acc[i][j][q] = 0.f;

    #pragma unroll
    for (int p = 0; p < 3; p++){
        uint32_t abuf = sb + ((p < 2) ? 0 : 16384);
        uint32_t bbuf = sb + 32768 + ((p == 1) ? 16384 : 0);
        #pragma unroll
        for (int kk = 0; kk < 4; kk++){
            uint32_t af[4][4];
            #pragma unroll
            for (int mt = 0; mt < 4; mt++){
                int m = wm + mt*16 + (lane & 7) + ((lane >> 3) & 1) * 8;
                int kc = kk*2 + (lane >> 4);
                ldm_x4(af[mt], abuf + (m << 7) + ((kc ^ (m & 7)) << 4));
            }
            uint32_t bfr[2][4];
            #pragma unroll
            for (int pr = 0; pr < 2; pr++){
                int n = wn + pr*16 + (lane & 7) + (lane >> 4) * 8;
                int kc = kk*2 + ((lane >> 3) & 1);
                ldm_x4(bfr[pr], bbuf + (n << 7) + ((kc ^ (n & 7)) << 4));
            }
            #pragma unroll
            for (int mt = 0; mt < 4; mt++)
                #pragma unroll
                for (int nt = 0; nt < 4; nt++)
                    mma_bf16(acc[mt][nt], af[mt], &bfr[nt >> 1][(nt & 1) * 2]);
        }
    }

    float* out = sc + (size_t)bh * Sn * Sn;
    int qrow = lane >> 2, qcol = (lane & 3) * 2;
    #pragma unroll
    for (int mt = 0; mt < 4; mt++)
        #pragma unroll
        for (int nt = 0; nt < 4; nt++)
            #pragma unroll
            for (int half = 0; half < 2; half++){
                int i = i0 + wm + mt*16 + qrow + half*8;
                int j = j0 + wn + nt*8 + qcol;
                float2 fv;
                fv.x = acc[mt][nt][half*2]   * 0.125f;
                fv.y = acc[mt][nt][half*2+1] * 0.125f;
                *(float2*)(out + (size_t)i*Sn + j) = fv;
            }
}

// ---------------- attn@V via HMMA (split probs x split V, trans-B) ----------
__global__ void __launch_bounds__(256) av_hmma(
    const bf16* __restrict__ ph, const bf16* __restrict__ pl,
    const bf16* __restrict__ vh, const bf16* __restrict__ vl,
    bf16* __restrict__ ah, bf16* __restrict__ al)
{
    int it = gridDim.x - 1 - blockIdx.x;     // big tiles scheduled first
    int bh = blockIdx.y, b = bh >> 3, h = bh & 7;
    int i0 = it * 128;

    extern __shared__ char smem[];
    uint32_t sb = smem_u32(smem);
    int tid = threadIdx.x, lane = tid & 31, wid = tid >> 5;

    const bf16* Ph = ph + (size_t)bh * Sn * Sn;
    const bf16* Pl = pl + (size_t)bh * Sn * Sn;
    const bf16* Vh = vh + (size_t)b*Sn*Dn + h*DKn;
    const bf16* Vl = vl + (size_t)b*Sn*Dn + h*DKn;

    const int nch = (it + 1) * 2;   // 64-wide j chunks
    const int T = 3 * nch;

    float acc[2][4][4];
    #pragma unroll
    for (int i = 0; i < 2; i++)
        #pragma unroll
        for (int j = 0; j < 4; j++)
            #pragma unroll
            for (int q = 0; q < 4; q++) acc[i][j][q] = 0.f;

    auto preload = [&](int t){
        int p = t / nch, c = t % nch, j0 = c << 6;
        const bf16* Ps = (p < 2)  ? Ph : Pl;
        const bf16* Vs = (p == 1) ? Vl : Vh;
        uint32_t buf = sb + (t & 1) * AV_STAGE;
        #pragma unroll
        for (int g = tid; g < 1024; g += 256){
            int r = g >> 3, ch = g & 7;
            cp16(buf + (r << 7) + ((ch ^ (r & 7)) << 4),
                 Ps + (size_t)(i0 + r) * Sn + j0 + ch * 8);
        }
        #pragma unroll
        for (int g = tid; g < 512; g += 256){
            int r = g >> 3, ch = g & 7;
            cp16(buf + 16384 + (r << 7) + ((ch ^ (r & 7)) << 4),
                 Vs + (size_t)(j0 + r) * Dn + ch * 8);
        }
        cp_commit();
    };

    preload(0);
    int wm = (wid >> 1) * 32, wn = (wid & 1) * 32;
    for (int t = 0; t < T; t++){
        cp_wait0();
        __syncthreads();
        if (t + 1 < T) preload(t + 1);

        uint32_t pb = sb + (t & 1) * AV_STAGE;
        uint32_t vb = pb + 16384;
        #pragma unroll
        for (int kk = 0; kk < 4; kk++){
            uint32_t af[2][4];
            #pragma unroll
            for (int mt = 0; mt < 2; mt++){
                int m = wm + mt*16 + (lane & 7) + ((lane >> 3) & 1) * 8;
                int kc = kk*2 + (lane >> 4);
                ldm_x4(af[mt], pb + (m << 7) + ((kc ^ (m & 7)) << 4));
            }
            uint32_t bfr[2][4];
            #pragma unroll
            for (int ng = 0; ng < 2; ng++){
                int row  = kk*16 + (lane & 7) + ((lane >> 3) & 1) * 8;
                int ncol = wn + ng*16 + ((lane >> 4) & 1) * 8;
                ldm_x4_t(bfr[ng], vb + (row << 7) + (((ncol >> 3) ^ (row & 7)) << 4));
            }
            #pragma unroll
            for (int mt = 0; mt < 2; mt++)
                #pragma unroll
                for (int nt = 0; nt < 4; nt++)
                    mma_bf16(acc[mt][nt], af[mt], &bfr[nt >> 1][(nt & 1) * 2]);
        }
        __syncthreads();
    }

    int qrow = lane >> 2, qcol = (lane & 3) * 2;
    #pragma unroll
    for (int mt = 0; mt < 2; mt++)
        #pragma unroll
        for (int nt = 0; nt < 4; nt++)
            #pragma unroll
            for (int half = 0; half < 2; half++){
                int i = i0 + wm + mt*16 + qrow + half*8;
                int d = wn + nt*8 + qcol;
                size_t off = (size_t)(b*Sn + i) * Dn + h*DKn + d;
                __nv_bfloat162 hp, lp;
                split2(acc[mt][nt][half*2], acc[mt][nt][half*2+1], hp, lp);
                *(__nv_bfloat162*)(ah + off) = hp;
                *(__nv_bfloat162*)(al + off) = lp;
            }
}

// ---------------- fused attention row pass (warp per row) -------------------
__global__ __launch_bounds__(256)
void attn_row(const float* __restrict__ sc, bf16* __restrict__ ph,
              bf16* __restrict__ pl, const float* __restrict__ gamma,
              int maskflag)
{
    const unsigned FULL = 0xffffffffu;
    int warp = (blockIdx.x * blockDim.x + threadIdx.x) >> 5;
    int lane = threadIdx.x & 31;
    int i = warp & (Sn-1);
    int h = (warp >> 9) & (Hn-1);
    const float* row = sc + (size_t)warp * Sn;
    int jbase = lane * 16;
    int jlim = ((i >> 7) + 1) << 7;
    bool act = jbase < jlim;
    int lim = maskflag ? i : (i - 1);

    float s[16];
    if (act){
        #pragma unroll
        for (int q = 0; q < 4; q++)
            *(float4*)&s[q*4] = *(const float4*)(row + jbase + q*4);
    } else {
        #pragma unroll
        for (int t = 0; t < 16; t++) s[t] = 0.f;
    }

    float m = -FLT_MAX;
    #pragma unroll
    for (int t = 0; t < 16; t++) if (jbase + t <= lim) m = fmaxf(m, s[t]);
    m = warp_max(m);

    float e[16]; float sum = 0.f;
    #pragma unroll
    for (int t = 0; t < 16; t++){
        e[t] = (jbase + t <= lim) ? __expf(s[t] - m) : 0.f;
        sum += e[t];
    }
    sum = warp_sum(sum);
    float inv1 = (sum > 0.f) ? 1.f / sum : 0.f;

    float c[16]; float run = 0.f;
    #pragma unroll
    for (int t = 0; t < 16; t++){ run += e[t]; c[t] = run; }
    float incl = run;
    #pragma unroll
    for (int o = 1; o < 32; o <<= 1){
        float tsh = __shfl_up_sync(FULL, incl, o);
        if (lane >= o) incl += tsh;
    }
    float excl = incl - run;

    float gm = gamma[h];
    float sp = (gm > 20.f) ? gm : log1pf(__expf(gm));
    float fi = (float)i;

    float s2[16];
    #pragma unroll
    for (int t = 0; t < 16; t++){
        float cumincl = excl + c[t];
        float rem = fmaxf(sum - cumincl, 0.f) * inv1;
        float pos = fabsf(fi - (float)(jbase + t));
        float dist = sqrtf(rem * pos);
        float eff = fminf(fmaxf(__expf(-sp * dist), 1e-5f), 1e5f);
        s2[t] = s[t] * eff;
    }

    float m2 = -FLT_MAX;
    #pragma unroll
    for (int t = 0; t < 16; t++) if (jbase + t <= lim) m2 = fmaxf(m2, s2[t]);
    m2 = warp_max(m2);

    float a[16]; float sum2 = 0.f;
    #pragma unroll
    for (int t = 0; t < 16; t++){
        a[t] = (jbase + t <= lim) ? __expf(s2[t] - m2) : 0.f;
        sum2 += a[t];
    }
    sum2 = warp_sum(sum2);
    float inv2 = (sum2 > 0.f) ? 1.f / sum2 : 0.f;
    if (!maskflag && i == 0) inv2 = 0.f;

    if (act){
        __nv_bfloat162 hp[8], lp[8];
        #pragma unroll
        for (int t = 0; t < 8; t++)
            split2(a[2*t] * inv2, a[2*t+1] * inv2, hp[t], lp[t]);
        bf16* pr = ph + (size_t)warp * Sn + jbase;
        bf16* lr = pl + (size_t)warp * Sn + jbase;
        *(uint4*)pr       = *(uint4*)&hp[0];
        *(uint4*)(pr + 8) = *(uint4*)&hp[4];
        *(uint4*)lr       = *(uint4*)&lp[0];
        *(uint4*)(lr + 8) = *(uint4*)&lp[4];
    }
}

// ---------------- residual + LayerNorm (+ bf16 split out) -------------------
__global__ __launch_bounds__(256)
void add_ln(const float* __restrict__ base, const float* __restrict__ delta,
            const float* __restrict__ g, const float* __restrict__ bt,
            float* __restrict__ out, bf16* __restrict__ oh, bf16* __restrict__ ol)
{
    long row = blockIdx.x;
    const float* x  = base  + row*Dn;
    const float* dl = delta + row*Dn;
    int t = threadIdx.x;
    __shared__ float red[32];

    float v0 = x[t]       + dl[t];
    float v1 = x[t + 256] + dl[t + 256];
    float s  = block_sum(v0 + v1, red);
    float sq = block_sum(v0*v0 + v1*v1, red);
    float mu  = s * (1.f/Dn);
    float var = sq * (1.f/Dn) - mu*mu;
    float inv = rsqrtf(var + 1e-5f);
    float o0 = (v0 - mu)*inv*g[t]       + bt[t];
    float o1 = (v1 - mu)*inv*g[t + 256] + bt[t + 256];
    out[row*Dn + t]       = o0;
    out[row*Dn + t + 256] = o1;
    bf16 h0 = __float2bfloat16(o0), h1 = __float2bfloat16(o1);
    oh[row*Dn + t]       = h0;
    oh[row*Dn + t + 256] = h1;
    ol[row*Dn + t]       = __float2bfloat16(o0 - __bfloat162float(h0));
    ol[row*Dn + t + 256] = __float2bfloat16(o1 - __bfloat162float(h1));
}

// ---------------- fp32 -> bf16 split ----------------------------------------
__global__ __launch_bounds__(256)
void k_split(const float* __restrict__ x, bf16* __restrict__ h,
             bf16* __restrict__ l, int n4)
{
    int i = blockIdx.x * blockDim.x + threadIdx.x;
    if (i >= n4) return;
    float4 v = ((const float4*)x)[i];
    __nv_bfloat162 hp0, hp1, lp0, lp1;
    split2(v.x, v.y, hp0, lp0);
    split2(v.z, v.w, hp1, lp1);
    ((__nv_bfloat162*)h)[2*i]   = hp0;
    ((__nv_bfloat162*)h)[2*i+1] = hp1;
    ((__nv_bfloat162*)l)[2*i]   = lp0;
    ((__nv_bfloat162*)l)[2*i+1] = lp1;
}

// ---------------- fp32 W[K,N] -> split bf16 W^T[N,K], batched over layers ---
__global__ __launch_bounds__(256)
void k_splitT(const float* __restrict__ W, bf16* __restrict__ hT,
              bf16* __restrict__ lT, int K, int N)
{
    size_t zoff = (size_t)blockIdx.z * K * N;
    W  += zoff; hT += zoff; lT += zoff;
    __shared__ float tile[32][33];
    int n0 = blockIdx.x * 32, k0 = blockIdx.y * 32;
    int tx = threadIdx.x & 31, ty = threadIdx.x >> 5;   // (32,8)
    #pragma unroll
    for (int i = 0; i < 32; i += 8)
        tile[ty+i][tx] = W[(size_t)(k0+ty+i)*N + n0+tx];
    __syncthreads();
    #pragma unroll
    for (int i = 0; i < 32; i += 8){
        float v = tile[tx][ty+i];
        size_t o = (size_t)(n0+ty+i)*K + k0+tx;
        bf16 h = __float2bfloat16(v);
        hT[o] = h;
        lT[o] = __float2bfloat16(v - __bfloat162float(h));
    }
}

// ---------------- host orchestration ----------------------------------------
static float* sym_addr(const void* s){
    void* p = nullptr;
    cudaGetSymbolAddress(&p, s);
    return (float*)p;
}
static bf16* sym_addr_b(const void* s){
    void* p = nullptr;
    cudaGetSymbolAddress(&p, s);
    return (bf16*)p;
}

extern "C" void kernel_launch(void* const* d_in, const int* in_sizes, int n_in,
                              void* d_out, int out_size)
{
    (void)in_sizes; (void)n_in; (void)out_size;
    const float* q_embed  = (const float*)d_in[0];
    const float* qa_embed = (const float*)d_in[1];
    const float* Wk    = (const float*)d_in[3];
    const float* bk    = (const float*)d_in[4];
    const float* Wv    = (const float*)d_in[5];
    const float* bv    = (const float*)d_in[6];
    const float* Wo    = (const float*)d_in[7];
    const float* bo    = (const float*)d_in[8];
    const float* gam   = (const float*)d_in[9];
    const float* ln1g  = (const float*)d_in[10];
    const float* ln1b  = (const float*)d_in[11];
    const float* W1    = (const float*)d_in[12];
    const float* b1    = (const float*)d_in[13];
    const float* W2    = (const float*)d_in[14];
    const float* b2    = (const float*)d_in[15];
    const float* ln2g  = (const float*)d_in[16];
    const float* ln2b  = (const float*)d_in[17];

    float* x   = sym_addr(g_x);
    float* y   = sym_addr(g_y);
    float* tmp = sym_addr(g_tmp);
    float* sc  = sym_addr(g_sc);
    bf16 *xh=sym_addr_b(g_xh), *xl=sym_addr_b(g_xl);
    bf16 *yh=sym_addr_b(g_yh), *yl=sym_addr_b(g_yl);
    bf16 *qkh=sym_addr_b(g_qkh), *qkl=sym_addr_b(g_qkl);
    bf16 *vph=sym_addr_b(g_vph), *vpl=sym_addr_b(g_vpl);
    bf16 *ah=sym_addr_b(g_ah), *al=sym_addr_b(g_al);
    bf16 *fh=sym_addr_b(g_fh), *fl=sym_addr_b(g_fl);
    bf16 *ph=sym_addr_b(g_ph), *pl=sym_addr_b(g_pl);
    bf16 *wkh=sym_addr_b(g_wkh), *wkl=sym_addr_b(g_wkl);
    bf16 *wvh=sym_addr_b(g_wvh), *wvl=sym_addr_b(g_wvl);
    bf16 *woh=sym_addr_b(g_woh), *wol=sym_addr_b(g_wol);
    bf16 *w1h=sym_addr_b(g_w1h), *w1l=sym_addr_b(g_w1l);
    bf16 *w2h=sym_addr_b(g_w2h), *w2l=sym_addr_b(g_w2l);

    // persistent side stream + fork/join events (created on first,
    // non-captured correctness call; reused identically every call)
    static cudaStream_t s1 = nullptr;
    static cudaEvent_t evF[Ln], evJ[Ln];
    if (s1 == nullptr){
        cudaStreamCreateWithFlags(&s1, cudaStreamNonBlocking);
        for (int i = 0; i < Ln; i++){
            cudaEventCreateWithFlags(&evF[i], cudaEventDisableTiming);
            cudaEventCreateWithFlags(&evJ[i], cudaEventDisableTiming);
        }
    }

    cudaFuncSetAttribute(hgemm<false,false,true>,
        cudaFuncAttributeMaxDynamicSharedMemorySize, HG_SMEM);
    cudaFuncSetAttribute(hgemm<true,true,false>,
        cudaFuncAttributeMaxDynamicSharedMemorySize, HG_SMEM);
    cudaFuncSetAttribute(hgemm<false,true,false>,
        cudaFuncAttributeMaxDynamicSharedMemorySize, HG_SMEM);
    cudaFuncSetAttribute(qk_hmma,
        cudaFuncAttributeMaxDynamicSharedMemorySize, QK_SMEM);
    cudaFuncSetAttribute(av_hmma,
        cudaFuncAttributeMaxDynamicSharedMemorySize, AV_SMEM);

    const size_t embBytes = (size_t)BSn*Dn*sizeof(float);
    cudaMemcpyAsync(x, q_embed,  embBytes, cudaMemcpyDeviceToDevice, 0);
    cudaMemcpyAsync(y, qa_embed, embBytes, cudaMemcpyDeviceToDevice, 0);

    // one-time weight transpose+split (batched over layers via grid.z)
    k_splitT<<<dim3(Dn/32,  Dn/32,  Ln), 256>>>(Wk, wkh, wkl, Dn,   Dn);
    k_splitT<<<dim3(Dn/32,  Dn/32,  Ln), 256>>>(Wv, wvh, wvl, Dn,   Dn);
    k_splitT<<<dim3(Dn/32,  Dn/32,  Ln), 256>>>(Wo, woh, wol, Dn,   Dn);
    k_splitT<<<dim3(DFFn/32,Dn/32,  Ln), 256>>>(W1, w1h, w1l, Dn,   DFFn);
    k_splitT<<<dim3(Dn/32, DFFn/32, Ln), 256>>>(W2, w2h, w2l, DFFn, Dn);

    k_split<<<(BSn*Dn/4+255)/256,256>>>(x, xh, xl, BSn*Dn/4);
    k_split<<<(BSn*Dn/4+255)/256,256>>>(y, yh, yl, BSn*Dn/4);

    auto tgM = [&](const bf16*Ah,const bf16*Al,const bf16*Bh,const bf16*Bl,
                   const float*bias, float*C, int N, int K){
        hgemm<false,false,true><<<dim3(N/128, BSn/128), 256, HG_SMEM>>>(
            Ah,Al,Bh,Bl,bias,C,nullptr,nullptr,N,K);
    };
    auto tgSplit = [&](const bf16*Ah,const bf16*Al,const bf16*Bh,const bf16*Bl,
                       const float*bias, bf16*Ch, bf16*Cl, int N, int K,
                       cudaStream_t st){
        hgemm<false,true,false><<<dim3(N/128, BSn/128), 256, HG_SMEM, st>>>(
            Ah,Al,Bh,Bl,bias,nullptr,Ch,Cl,N,K);
    };
    auto tgRelu = [&](const bf16*Ah,const bf16*Al,const bf16*Bh,const bf16*Bl,
                      const float*bias, bf16*Ch, bf16*Cl, int N, int K){
        hgemm<true,true,false><<<dim3(N/128, BSn/128), 256, HG_SMEM>>>(
            Ah,Al,Bh,Bl,bias,nullptr,Ch,Cl,N,K);
    };

    auto layer = [&](int l, float* q, bf16* qh, bf16* ql,
                     const bf16* vsh, const bf16* vsl, int maskflag, bool pos){
        long oD = (long)l*Dn*Dn, oF = (long)l*Dn*DFFn;

        // fork: V projection runs on s1, overlapping qk_hmma + attn_row
        cudaEventRecord(evF[l], 0);
        cudaStreamWaitEvent(s1, evF[l], 0);
        tgSplit(vsh, vsl, wvh+oD, wvl+oD, bv + (long)l*Dn, vph, vpl, Dn, Dn, s1);

        // main stream: Q/K projection -> scores -> softmax chain
        tgSplit(qh,  ql,  wkh+oD, wkl+oD, bk + (long)l*Dn, qkh, qkl, Dn, Dn, 0);
        qk_hmma<<<dim3(4, 4, Bn*Hn), 256, QK_SMEM>>>(qkh, qkl, sc);
        attn_row<<<dim3(Bn*Hn*Sn/8, 1, 1), 256>>>(sc, ph, pl,
                                                  gam + (long)l*Hn, maskflag);

        // join: av needs V projection results
        cudaEventRecord(evJ[l], s1);
        cudaStreamWaitEvent(0, evJ[l], 0);
        av_hmma<<<dim3(4, Bn*Hn), 256, AV_SMEM>>>(ph, pl, vph, vpl, ah, al);

        tgM(ah, al, woh+oD, wol+oD, bo + (long)l*Dn, tmp, Dn, Dn);
        add_ln<<<BSn,256>>>(q, tmp, ln1g + (long)l*Dn, ln1b + (long)l*Dn, q, qh, ql);

        if (pos){
            tgRelu(qh, ql, w1h+oF, w1l+oF, b1 + (long)l*DFFn, fh, fl, DFFn, Dn);
            tgM(fh, fl, w2h+oF, w2l+oF, b2 + (long)l*Dn, tmp, Dn, DFFn);
            add_ln<<<BSn,256>>>(q, tmp, ln2g + (long)l*Dn, ln2b + (long)l*Dn, q, qh, ql);
        }
    };

    // blocks_1: self-attn on y, mask=1, FFN
    layer(0, y, yh, yl, yh, yl, 1, true);
    layer(1, y, yh, yl, yh, yl, 1, true);
    // blocks_2: (mask=1, no FFN) then (mask=0, values=y, FFN)
    layer(2, x, xh, xl, xh, xl, 1, false);
    layer(3, x, xh, xl, yh, yl, 0, true);
    layer(4, x, xh, xl, xh, xl, 1, false);
    layer(5, x, xh, xl, yh, yl, 0, true);

    cudaMemcpyAsync(d_out, x, embBytes, cudaMemcpyDeviceToDevice, 0);
    cudaMemcpyAsync((char*)d_out + embBytes, y, embBytes, cudaMemcpyDeviceToDevice, 0);
}